// round 15
// baseline (speedup 1.0000x reference)
#include <cuda_runtime.h>
#include <cuda_fp16.h>
#include <math.h>
#include <stdint.h>

#define S_LEN 2048
#define BATCH 2
#define EMB   1024
#define NH    16
#define DH    64
#define PP    64
#define FF    4096
#define NROWS (S_LEN*BATCH)   // 4096
#define BH    (BATCH*NH)      // 32

// ---------------- scratch (static device allocations) ----------------
__device__ __align__(16) float g_pe[BATCH*PP*S_LEN];
__device__ __align__(16) float g_possim[(size_t)BATCH*S_LEN*S_LEN];
__device__ __align__(16) float g_qkv[(size_t)NROWS*3*EMB];
__device__ __align__(16) float g_tmp[(size_t)NROWS*EMB];
__device__ __align__(16) float g_x[(size_t)NROWS*EMB];

// fp16 split operand buffers (A-side: hi+lo; B-side weights: hi only)
__device__ __align__(16) __half g_src_hi[(size_t)NROWS*EMB],  g_src_lo[(size_t)NROWS*EMB];
__device__ __align__(16) __half g_ctx_hi[(size_t)NROWS*EMB],  g_ctx_lo[(size_t)NROWS*EMB];
__device__ __align__(16) __half g_x_hi[(size_t)NROWS*EMB],    g_x_lo[(size_t)NROWS*EMB];
__device__ __align__(16) __half g_ff1_hi[(size_t)NROWS*FF],   g_ff1_lo[(size_t)NROWS*FF];
__device__ __align__(16) __half g_ipw_hi[(size_t)3*EMB*EMB];
__device__ __align__(16) __half g_outw_hi[(size_t)EMB*EMB];
__device__ __align__(16) __half g_l1w_hi[(size_t)FF*EMB];
__device__ __align__(16) __half g_l2w_hi[(size_t)EMB*FF];

// flash-attn operands: q = 0.125*q (hi+lo), k (hi), V^T (hi), all [bh][s|d][64|t]
__device__ __align__(16) __half g_qe_hi[(size_t)BH*S_LEN*DH], g_qe_lo[(size_t)BH*S_LEN*DH];
__device__ __align__(16) __half g_ke_hi[(size_t)BH*S_LEN*DH];
__device__ __align__(16) __half g_vt_hi[(size_t)BH*DH*S_LEN];

// ---------------- helpers ----------------
__device__ __forceinline__ uint32_t smem_u32(const void* p) {
    uint32_t a;
    asm("{ .reg .u64 t; cvta.to.shared.u64 t, %1; cvt.u32.u64 %0, t; }" : "=r"(a) : "l"(p));
    return a;
}
__device__ __forceinline__ void ldm_x4(uint32_t* r, uint32_t addr) {
    asm volatile("ldmatrix.sync.aligned.m8n8.x4.shared.b16 {%0,%1,%2,%3}, [%4];"
        : "=r"(r[0]), "=r"(r[1]), "=r"(r[2]), "=r"(r[3]) : "r"(addr));
}
__device__ __forceinline__ void mma16816(float* c, const uint32_t* a, uint32_t b0, uint32_t b1) {
    asm volatile("mma.sync.aligned.m16n8k16.row.col.f32.f16.f16.f32 "
        "{%0,%1,%2,%3}, {%4,%5,%6,%7}, {%8,%9}, {%0,%1,%2,%3};"
        : "+f"(c[0]), "+f"(c[1]), "+f"(c[2]), "+f"(c[3])
        : "r"(a[0]), "r"(a[1]), "r"(a[2]), "r"(a[3]), "r"(b0), "r"(b1));
}
__device__ __forceinline__ uint32_t pack_f16x2(float a, float b) {
    uint32_t r;
    asm("cvt.rn.f16x2.f32 %0, %1, %2;" : "=r"(r) : "f"(b), "f"(a));
    return r;
}
#define CP_ASYNC16(s, g) \
    asm volatile("cp.async.cg.shared.global [%0], [%1], 16;" :: "r"(s), "l"(g))
#define CP_COMMIT() asm volatile("cp.async.commit_group;" ::: "memory")

__device__ __forceinline__ float warp_sum(float v) {
    #pragma unroll
    for (int o = 16; o; o >>= 1) v += __shfl_xor_sync(0xffffffffu, v, o);
    return v;
}

// ---------------- fp32 -> (hi, lo) fp16 split, elementwise ----------------
__global__ __launch_bounds__(256) void k_split(const float4* __restrict__ in,
                                               __half2* __restrict__ hi,
                                               __half2* __restrict__ lo, int n4) {
    int i = blockIdx.x * 256 + threadIdx.x;
    if (i >= n4) return;
    float4 v = in[i];
    __half hx = __float2half(v.x), hy = __float2half(v.y);
    __half hz = __float2half(v.z), hw = __float2half(v.w);
    __half2 h0; h0.x = hx; h0.y = hy;
    __half2 h1; h1.x = hz; h1.y = hw;
    __half2 l0; l0.x = __float2half(v.x - __half2float(hx));
                l0.y = __float2half(v.y - __half2float(hy));
    __half2 l1; l1.x = __float2half(v.z - __half2float(hz));
                l1.y = __float2half(v.w - __half2float(hw));
    hi[2*i] = h0; hi[2*i+1] = h1;
    lo[2*i] = l0; lo[2*i+1] = l1;
}

// fp32 -> fp16 hi only (weights / B-side)
__global__ __launch_bounds__(256) void k_split_hi(const float4* __restrict__ in,
                                                  __half2* __restrict__ hi, int n4) {
    int i = blockIdx.x * 256 + threadIdx.x;
    if (i >= n4) return;
    float4 v = in[i];
    __half2 h0; h0.x = __float2half(v.x); h0.y = __float2half(v.y);
    __half2 h1; h1.x = __float2half(v.z); h1.y = __float2half(v.w);
    hi[2*i] = h0; hi[2*i+1] = h1;
}

// ---------------- HMMA fp16 GEMM (A split optional), 3-stage pipeline ----------------
#define GT_TILE  10240            // 128 rows * 80 B
#define GT_STAGE (3*GT_TILE)      // Ahi, Alo, Bhi = 30720
#define GT_SMEM  (3*GT_STAGE)     // 92160 B (3 stages)

template<bool RELU, bool SPLIT, bool F32OUT, bool ALO>
__global__ __launch_bounds__(256) void hmma_gemm(
    const __half* __restrict__ Ahi, const __half* __restrict__ Alo,
    const __half* __restrict__ Bhi,
    const float* __restrict__ bias,
    float* __restrict__ C, __half* __restrict__ Chi, __half* __restrict__ Clo,
    int M, int N, int K)
{
    extern __shared__ __align__(16) char smem[];
    const uint32_t sb = smem_u32(smem);
    const int tid = threadIdx.x;
    const int lane = tid & 31, wid = tid >> 5;
    const int wm = wid >> 1, wn = wid & 1;
    const int bm = blockIdx.y * 128, bn = blockIdx.x * 128;
    const int NC = K >> 5;

    auto load_chunk = [&](int c, int buf) {
        const int k0 = c << 5;
        const uint32_t st = sb + buf * GT_STAGE;
        const __half* gp[3] = { Ahi, Alo, Bhi };
        #pragma unroll
        for (int t = 0; t < 3; ++t) {
            if (!ALO && t == 1) continue;
            const int base = (t < 2) ? bm : bn;
            const uint32_t toff = st + t * GT_TILE;
            #pragma unroll
            for (int l = 0; l < 2; ++l) {
                int i = tid + l * 256;
                int r = i >> 2, q = i & 3;
                const __half* g = gp[t] + (size_t)(base + r) * K + k0 + q * 8;
                CP_ASYNC16(toff + r * 80 + q * 16, g);
            }
        }
        CP_COMMIT();
    };

    float acc[2][8][4] = {};
    const uint32_t lm_off = (lane & 15) * 80 + ((lane >> 4) << 4);

    load_chunk(0, 0);
    if (NC > 1) load_chunk(1, 1);

    for (int c = 0; c < NC; ++c) {
        const int buf = c % 3;
        if (c + 2 < NC) {
            load_chunk(c + 2, (c + 2) % 3);
            asm volatile("cp.async.wait_group 2;" ::: "memory");
        } else if (c + 1 < NC) {
            asm volatile("cp.async.wait_group 1;" ::: "memory");
        } else {
            asm volatile("cp.async.wait_group 0;" ::: "memory");
        }
        __syncthreads();

        const uint32_t st = sb + buf * GT_STAGE;
        const uint32_t ah = st + (wm * 32) * 80 + lm_off;
        const uint32_t al = st + GT_TILE + (wm * 32) * 80 + lm_off;
        const uint32_t bb = st + 2 * GT_TILE + (wn * 64) * 80 + lm_off;
        #pragma unroll
        for (int ks = 0; ks < 2; ++ks) {
            uint32_t arh[2][4], arl[2][4], br[4][4];
            #pragma unroll
            for (int im = 0; im < 2; ++im) {
                ldm_x4(arh[im], ah + im * 16 * 80 + ks * 32);
                if (ALO) ldm_x4(arl[im], al + im * 16 * 80 + ks * 32);
            }
            #pragma unroll
            for (int ng = 0; ng < 4; ++ng)
                ldm_x4(br[ng], bb + ng * 16 * 80 + ks * 32);
            #pragma unroll
            for (int im = 0; im < 2; ++im)
                #pragma unroll
                for (int ng = 0; ng < 4; ++ng) {
                    mma16816(acc[im][2*ng+0], arh[im], br[ng][0], br[ng][2]);
                    mma16816(acc[im][2*ng+1], arh[im], br[ng][1], br[ng][3]);
                }
            if (ALO) {
                #pragma unroll
                for (int im = 0; im < 2; ++im)
                    #pragma unroll
                    for (int ng = 0; ng < 4; ++ng) {
                        mma16816(acc[im][2*ng+0], arl[im], br[ng][0], br[ng][2]);
                        mma16816(acc[im][2*ng+1], arl[im], br[ng][1], br[ng][3]);
                    }
            }
        }
        __syncthreads();
    }

    const int r0 = bm + wm * 32 + (lane >> 2);
    const int c0 = bn + wn * 64 + (lane & 3) * 2;
    #pragma unroll
    for (int im = 0; im < 2; ++im) {
        #pragma unroll
        for (int n8 = 0; n8 < 8; ++n8) {
            const int col = c0 + n8 * 8;
            const float b0 = bias[col], b1 = bias[col + 1];
            #pragma unroll
            for (int half_ = 0; half_ < 2; ++half_) {
                const int row = r0 + im * 16 + half_ * 8;
                float v0 = acc[im][n8][half_*2+0] + b0;
                float v1 = acc[im][n8][half_*2+1] + b1;
                if (RELU) { v0 = fmaxf(v0, 0.f); v1 = fmaxf(v1, 0.f); }
                if (F32OUT) {
                    *(float2*)(C + (size_t)row * N + col) = make_float2(v0, v1);
                }
                if (SPLIT) {
                    __half h0 = __float2half(v0);
                    __half h1 = __float2half(v1);
                    __half2 hh; hh.x = h0; hh.y = h1;
                    __half2 ll;
                    ll.x = __float2half(v0 - __half2float(h0));
                    ll.y = __float2half(v1 - __half2float(h1));
                    *(__half2*)(Chi + (size_t)row * N + col) = hh;
                    *(__half2*)(Clo + (size_t)row * N + col) = ll;
                }
            }
        }
    }
}

// ---------------- pe = pos_w @ pos_embed + pos_b ----------------
__global__ __launch_bounds__(256) void k_pe(const float* __restrict__ pos_embed,
                                            const float* __restrict__ pos_w,
                                            const float* __restrict__ pos_b) {
    int n = blockIdx.x * 256 + threadIdx.x;
    if (n >= BATCH*PP*S_LEN) return;
    int s = n % S_LEN;
    int q = (n / S_LEN) % PP;
    int b = n / (S_LEN * PP);
    const float* pw = pos_w + q * PP;
    const float* pem = pos_embed + (size_t)b * PP * S_LEN + s;
    float acc = pos_b[q];
    #pragma unroll 8
    for (int p = 0; p < PP; ++p) acc = fmaf(pw[p], pem[(size_t)p * S_LEN], acc);
    g_pe[n] = acc;
}

// ---------------- L1 normalize pe over q-axis ----------------
__global__ __launch_bounds__(256) void k_l1() {
    int n = blockIdx.x * 256 + threadIdx.x;
    if (n >= BATCH * S_LEN) return;
    int b = n / S_LEN, s = n % S_LEN;
    float* base = g_pe + (size_t)b * PP * S_LEN + s;
    float sum = 0.f;
    #pragma unroll 8
    for (int q = 0; q < PP; ++q) sum += fabsf(base[(size_t)q * S_LEN]);
    float inv = 1.0f / fmaxf(sum, 1e-12f);
    #pragma unroll 8
    for (int q = 0; q < PP; ++q) base[(size_t)q * S_LEN] *= inv;
}

// ---------------- pos_sim[b,s,t] = sum_q pe[b,q,s]*pe[b,q,t] (exact fp32) ----------------
__global__ __launch_bounds__(256) void k_possim() {
    __shared__ float Ps[PP][65];
    __shared__ float Pt[PP][65];
    int b = blockIdx.z;
    int t0 = blockIdx.x * 64, s0 = blockIdx.y * 64;
    int tid = threadIdx.x;
    const float* peb = g_pe + (size_t)b * PP * S_LEN;
    #pragma unroll
    for (int l = 0; l < 4; ++l) {
        int i = tid + l * 256;
        int q = i >> 4, cq = i & 15;
        float4 v = *(const float4*)(peb + (size_t)q * S_LEN + s0 + cq * 4);
        Ps[q][cq*4+0] = v.x; Ps[q][cq*4+1] = v.y; Ps[q][cq*4+2] = v.z; Ps[q][cq*4+3] = v.w;
        float4 w = *(const float4*)(peb + (size_t)q * S_LEN + t0 + cq * 4);
        Pt[q][cq*4+0] = w.x; Pt[q][cq*4+1] = w.y; Pt[q][cq*4+2] = w.z; Pt[q][cq*4+3] = w.w;
    }
    __syncthreads();
    int ty = tid / 16, tx = tid % 16;
    float acc[4][4] = {};
    #pragma unroll 8
    for (int q = 0; q < PP; ++q) {
        float a[4], c[4];
        #pragma unroll
        for (int i = 0; i < 4; ++i) a[i] = Ps[q][ty*4+i];
        #pragma unroll
        for (int j = 0; j < 4; ++j) c[j] = Pt[q][tx*4+j];
        #pragma unroll
        for (int i = 0; i < 4; ++i)
            #pragma unroll
            for (int j = 0; j < 4; ++j) acc[i][j] = fmaf(a[i], c[j], acc[i][j]);
    }
    #pragma unroll
    for (int i = 0; i < 4; ++i) {
        int sr = s0 + ty*4 + i;
        float4 o = make_float4(acc[i][0], acc[i][1], acc[i][2], acc[i][3]);
        *(float4*)(g_possim + ((size_t)b * S_LEN + sr) * S_LEN + t0 + tx*4) = o;
    }
}

// ---------------- build q (hi/lo, pre-scaled) and k (hi), [bh][s][64] ----------------
__global__ __launch_bounds__(256) void k_prepqk() {
    int idx = blockIdx.x * 256 + threadIdx.x;          // over BH*S*16
    if (idx >= BH * S_LEN * 16) return;
    int j4 = (idx & 15) * 4;
    int s  = (idx >> 4) & (S_LEN - 1);
    int bh = idx >> 15;
    int b = bh / NH, h = bh % NH;
    size_t qbase = ((size_t)s * BATCH + b) * (3*EMB) + h * DH + j4;
    size_t obase = ((size_t)bh * S_LEN + s) * DH + j4;
    #pragma unroll
    for (int u = 0; u < 4; ++u) {
        float qv = 0.125f * g_qkv[qbase + u];
        float kv = g_qkv[qbase + EMB + u];
        __half qh = __float2half(qv);
        g_qe_hi[obase + u] = qh;
        g_qe_lo[obase + u] = __float2half(qv - __half2float(qh));
        g_ke_hi[obase + u] = __float2half(kv);
    }
}

// ---------------- build V^T [bh][d][t] (hi) ----------------
__global__ __launch_bounds__(256) void k_prepv() {
    int idx = blockIdx.x * 256 + threadIdx.x;          // over BH*64*(S/4)
    if (idx >= BH * DH * (S_LEN/4)) return;
    int t4 = (idx & (S_LEN/4 - 1)) * 4;
    int d  = (idx >> 9) & 63;
    int bh = idx >> 15;
    int b = bh / NH, h = bh % NH;
    size_t obase = ((size_t)bh * DH + d) * S_LEN + t4;
    #pragma unroll
    for (int u = 0; u < 4; ++u) {
        int t = t4 + u;
        float v = g_qkv[((size_t)t * BATCH + b) * (3*EMB) + 2*EMB + h*DH + d];
        g_vt_hi[obase + u] = __float2half(v);
    }
}

// ---------------- fused flash attention (K=64, pos_sim prefetched from gmem) ----------------
#define FL_KV    20480
#define FL_VHI   10240
#define FL_QOFF  (2*FL_KV)         // 40960
#define FL_QLO   20480
#define FL_SMEM  (FL_QOFF + 40960) // 81920

__global__ __launch_bounds__(256, 1) void k_flash() {
    extern __shared__ __align__(16) char smem[];
    const uint32_t sb = smem_u32(smem);
    const int tid = threadIdx.x, lane = tid & 31, w = tid >> 5;
    const int s0 = blockIdx.x * 128;
    const int bh = blockIdx.y;
    const int b = bh / NH, h = bh % NH;
    const uint32_t lm = (lane & 15) * 80 + ((lane >> 4) << 4);

    // ---- async load q tile (128 rows x 64 K, hi+lo) ----
    const __half* qhg = g_qe_hi + ((size_t)bh * S_LEN + s0) * DH;
    const __half* qlg = g_qe_lo + ((size_t)bh * S_LEN + s0) * DH;
    #pragma unroll
    for (int l = 0; l < 4; ++l) {
        int i = tid + l * 256;            // [0,1024): r=i/8, q=i%8
        int r = i >> 3, q = i & 7;
        int kc = q >> 2, qq = q & 3;
        CP_ASYNC16(sb + FL_QOFF + kc*10240 + r*80 + qq*16, qhg + (size_t)r*DH + kc*32 + qq*8);
        CP_ASYNC16(sb + FL_QOFF + FL_QLO + kc*10240 + r*80 + qq*16, qlg + (size_t)r*DH + kc*32 + qq*8);
    }
    CP_COMMIT();

    // kv chunk loader: 64 t-rows of k hi (K=64) + 64 d-rows of V^T hi (t-chunk 64)
    auto load_kv = [&](int c, int buf) {
        const uint32_t kb = sb + buf * FL_KV;
        const __half* khg = g_ke_hi + ((size_t)bh * S_LEN + c*64) * DH;
        #pragma unroll
        for (int l = 0; l < 2; ++l) {
            int i = tid + l * 256;        // [0,512): r=i/8, q=i%8
            int r = i >> 3, q = i & 7;
            int kc = q >> 2, qq = q & 3;
            CP_ASYNC16(kb + kc*5120 + r*80 + qq*16, khg + (size_t)r*DH + kc*32 + qq*8);
        }
        const __half* vhg = g_vt_hi + (size_t)bh * DH * S_LEN + c*64;
        #pragma unroll
        for (int l = 0; l < 2; ++l) {
            int i = tid + l * 256;        // [0,512): r=i/8, q=i%8
            int r = i >> 3, q = i & 7;
            int kc = q >> 2, qq = q & 3;
            CP_ASYNC16(kb + FL_VHI + kc*5120 + r*80 + qq*16, vhg + (size_t)r*S_LEN + kc*32 + qq*8);
        }
        CP_COMMIT();
    };

    load_kv(0, 0);
    asm volatile("cp.async.wait_group 0;" ::: "memory");
    __syncthreads();

    // ---- extract q A-fragments into registers (4 k16-slices, hi+lo) ----
    uint32_t aqh[4][4], aql[4][4];
    #pragma unroll
    for (int ks4 = 0; ks4 < 4; ++ks4) {
        int kc = ks4 >> 1, ks = ks4 & 1;
        ldm_x4(aqh[ks4], sb + FL_QOFF + kc*10240 + (w*16)*80 + lm + ks*32);
        ldm_x4(aql[ks4], sb + FL_QOFF + FL_QLO + kc*10240 + (w*16)*80 + lm + ks*32);
    }

    // pos_sim row pointers for this thread's two C-fragment rows
    const float* pr0 = g_possim + ((size_t)b * S_LEN + (s0 + w*16 + (lane >> 2))) * S_LEN + (lane & 3) * 2;
    const float* pr1 = pr0 + (size_t)8 * S_LEN;

    float octx[8][4] = {};
    float m0 = -1e30f, m1 = -1e30f, l0 = 0.f, l1 = 0.f;
    const int NC = S_LEN / 64;

    for (int c = 0; c < NC; ++c) {
        const int buf = c & 1;
        if (c + 1 < NC) {
            load_kv(c + 1, buf ^ 1);
            asm volatile("cp.async.wait_group 1;" ::: "memory");
        } else {
            asm volatile("cp.async.wait_group 0;" ::: "memory");
        }
        __syncthreads();
        const uint32_t kb = sb + buf * FL_KV;

        // ---- prefetch pos_sim (exact fp32, L2-resident) to overlap with QK MMAs ----
        float2 pf0[8], pf1[8];
        {
            const float* p0 = pr0 + c * 64;
            const float* p1 = pr1 + c * 64;
            #pragma unroll
            for (int ng = 0; ng < 8; ++ng) {
                pf0[ng] = *(const float2*)(p0 + ng * 8);
                pf1[ng] = *(const float2*)(p1 + ng * 8);
            }
        }

        // ---- QK: P[16 x 64] = q * k^T  (2-pass split on q, K=64) ----
        float ps[8][4] = {};
        #pragma unroll
        for (int ks4 = 0; ks4 < 4; ++ks4) {
            int kc = ks4 >> 1, ks = ks4 & 1;
            uint32_t bh4[4][4];
            #pragma unroll
            for (int ng = 0; ng < 4; ++ng)
                ldm_x4(bh4[ng], kb + kc*5120 + (ng*16)*80 + lm + ks*32);
            #pragma unroll
            for (int ng = 0; ng < 4; ++ng) {
                mma16816(ps[2*ng],   aqh[ks4], bh4[ng][0], bh4[ng][2]);
                mma16816(ps[2*ng+1], aqh[ks4], bh4[ng][1], bh4[ng][3]);
                mma16816(ps[2*ng],   aql[ks4], bh4[ng][0], bh4[ng][2]);
                mma16816(ps[2*ng+1], aql[ks4], bh4[ng][1], bh4[ng][3]);
            }
        }

        // ---- add prefetched pos_sim ----
        #pragma unroll
        for (int ng = 0; ng < 8; ++ng) {
            ps[ng][0] += pf0[ng].x; ps[ng][1] += pf0[ng].y;
            ps[ng][2] += pf1[ng].x; ps[ng][3] += pf1[ng].y;
        }

        // ---- online softmax (rows: half0 = lane/4, half1 = +8) ----
        float mx0 = -1e30f, mx1 = -1e30f;
        #pragma unroll
        for (int ng = 0; ng < 8; ++ng) {
            mx0 = fmaxf(mx0, fmaxf(ps[ng][0], ps[ng][1]));
            mx1 = fmaxf(mx1, fmaxf(ps[ng][2], ps[ng][3]));
        }
        mx0 = fmaxf(mx0, __shfl_xor_sync(0xffffffffu, mx0, 1));
        mx0 = fmaxf(mx0, __shfl_xor_sync(0xffffffffu, mx0, 2));
        mx1 = fmaxf(mx1, __shfl_xor_sync(0xffffffffu, mx1, 1));
        mx1 = fmaxf(mx1, __shfl_xor_sync(0xffffffffu, mx1, 2));
        float mn0 = fmaxf(m0, mx0), mn1 = fmaxf(m1, mx1);
        float sc0 = __expf(m0 - mn0), sc1 = __expf(m1 - mn1);
        m0 = mn0; m1 = mn1;
        l0 *= sc0; l1 *= sc1;
        #pragma unroll
        for (int ng = 0; ng < 8; ++ng) {
            octx[ng][0] *= sc0; octx[ng][1] *= sc0;
            octx[ng][2] *= sc1; octx[ng][3] *= sc1;
        }
        float rs0 = 0.f, rs1 = 0.f;
        #pragma unroll
        for (int ng = 0; ng < 8; ++ng) {
            ps[ng][0] = __expf(ps[ng][0] - mn0);
            ps[ng][1] = __expf(ps[ng][1] - mn0);
            ps[ng][2] = __expf(ps[ng][2] - mn1);
            ps[ng][3] = __expf(ps[ng][3] - mn1);
            rs0 += ps[ng][0] + ps[ng][1];
            rs1 += ps[ng][2] + ps[ng][3];
        }
        rs0 += __shfl_xor_sync(0xffffffffu, rs0, 1);
        rs0 += __shfl_xor_sync(0xffffffffu, rs0, 2);
        rs1 += __shfl_xor_sync(0xffffffffu, rs1, 1);
        rs1 += __shfl_xor_sync(0xffffffffu, rs1, 2);
        l0 += rs0; l1 += rs1;

        // ---- register C-frag -> A-frag conversion (P hi only) ----
        uint32_t aph[4][4];
        #pragma unroll
        for (int kj = 0; kj < 4; ++kj) {
            #pragma unroll
            for (int q = 0; q < 4; ++q) {
                int nb = 2*kj + (q >> 1);
                float e0 = ps[nb][(q & 1) * 2 + 0];
                float e1 = ps[nb][(q & 1) * 2 + 1];
                aph[kj][q] = pack_f16x2(e0, e1);
            }
        }

        // ---- PV: ctx += P * V  (single-pass), B = V^T hi ----
        #pragma unroll
        for (int kj = 0; kj < 4; ++kj) {
            int kc = kj >> 1, ks = kj & 1;
            uint32_t vh4[4][4];
            #pragma unroll
            for (int ng = 0; ng < 4; ++ng)
                ldm_x4(vh4[ng], kb + FL_VHI + kc*5120 + (ng*16)*80 + lm + ks*32);
            #pragma unroll
            for (int ng = 0; ng < 4; ++ng) {
                mma16816(octx[2*ng],   aph[kj], vh4[ng][0], vh4[ng][2]);
                mma16816(octx[2*ng+1], aph[kj], vh4[ng][1], vh4[ng][3]);
            }
        }
        __syncthreads();
    }

    // ---- epilogue: normalize, write ctx hi/lo (layout [(s*B+b)*E + h*64 + d]) ----
    float i0 = 1.f / l0, i1 = 1.f / l1;
    const int g = lane >> 2;
    #pragma unroll
    for (int half_ = 0; half_ < 2; ++half_) {
        const int s = s0 + w * 16 + g + half_ * 8;
        const float ih = half_ ? i1 : i0;
        size_t base = ((size_t)s * BATCH + b) * EMB + h * DH;
        #pragma unroll
        for (int ng = 0; ng < 8; ++ng) {
            int col = ng * 8 + (lane & 3) * 2;
            float v0 = octx[ng][half_*2+0] * ih;
            float v1 = octx[ng][half_*2+1] * ih;
            __half h0 = __float2half(v0);
            __half h1 = __float2half(v1);
            __half2 hh; hh.x = h0; hh.y = h1;
            __half2 ll;
            ll.x = __float2half(v0 - __half2float(h0));
            ll.y = __float2half(v1 - __half2float(h1));
            *(__half2*)(g_ctx_hi + base + col) = hh;
            *(__half2*)(g_ctx_lo + base + col) = ll;
        }
    }
}

// ---------------- out = LayerNorm(A + B), optional fp16 split emission ----------------
template<bool SPLIT>
__global__ __launch_bounds__(256) void k_ln(const float* __restrict__ A,
                                            const float* __restrict__ Bv,
                                            const float* __restrict__ gam,
                                            const float* __restrict__ bet,
                                            float* __restrict__ out,
                                            __half* __restrict__ ohi,
                                            __half* __restrict__ olo) {
    __shared__ float red[8];
    size_t row = blockIdx.x;
    const float* a = A + row * EMB;
    const float* b = Bv + row * EMB;
    int tid = threadIdx.x;
    int lane = tid & 31, wid = tid >> 5;
    float v[4];
    float sum = 0.f;
    #pragma unroll
    for (int i = 0; i < 4; ++i) { v[i] = a[tid + i*256] + b[tid + i*256]; sum += v[i]; }
    sum = warp_sum(sum);
    if (lane == 0) red[wid] = sum;
    __syncthreads();
    if (wid == 0) {
        float t = (lane < 8) ? red[lane] : 0.f;
        t = warp_sum(t);
        if (lane == 0) red[0] = t;
    }
    __syncthreads();
    float mu = red[0] * (1.0f / EMB);
    __syncthreads();
    float sq = 0.f;
    #pragma unroll
    for (int i = 0; i < 4; ++i) { float d = v[i] - mu; sq += d * d; }
    sq = warp_sum(sq);
    if (lane == 0) red[wid] = sq;
    __syncthreads();
    if (wid == 0) {
        float t = (lane < 8) ? red[lane] : 0.f;
        t = warp_sum(t);
        if (lane == 0) red[0] = t;
    }
    __syncthreads();
    float inv = rsqrtf(red[0] * (1.0f / EMB) + 1e-5f);
    #pragma unroll
    for (int i = 0; i < 4; ++i) {
        int c = tid + i*256;
        float o = (v[i] - mu) * inv * gam[c] + bet[c];
        out[row * EMB + c] = o;
        if (SPLIT) {
            __half h = __float2half(o);
            ohi[row * EMB + c] = h;
            olo[row * EMB + c] = __float2half(o - __half2float(h));
        }
    }
}

// ---------------- launch ----------------
extern "C" void kernel_launch(void* const* d_in, const int* in_sizes, int n_in,
                              void* d_out, int out_size) {
    const float* src       = (const float*)d_in[0];
    const float* pos_embed = (const float*)d_in[1];
    const float* in_proj_w = (const float*)d_in[2];
    const float* in_proj_b = (const float*)d_in[3];
    const float* out_w     = (const float*)d_in[4];
    const float* out_b     = (const float*)d_in[5];
    const float* lin1_w    = (const float*)d_in[6];
    const float* lin1_b    = (const float*)d_in[7];
    const float* lin2_w    = (const float*)d_in[8];
    const float* lin2_b    = (const float*)d_in[9];
    const float* ln1_g     = (const float*)d_in[10];
    const float* ln1_b     = (const float*)d_in[11];
    const float* ln2_g     = (const float*)d_in[12];
    const float* ln2_b     = (const float*)d_in[13];
    const float* pos_w     = (const float*)d_in[14];
    const float* pos_b     = (const float*)d_in[15];
    float* out = (float*)d_out;

    float *p_qkv, *p_tmp, *p_x;
    __half *p_src_hi, *p_src_lo, *p_ctx_hi, *p_ctx_lo, *p_x_hi, *p_x_lo;
    __half *p_ff1_hi, *p_ff1_lo;
    __half *p_ipw_hi, *p_outw_hi, *p_l1w_hi, *p_l2w_hi;
    cudaGetSymbolAddress((void**)&p_qkv, g_qkv);
    cudaGetSymbolAddress((void**)&p_tmp, g_tmp);
    cudaGetSymbolAddress((void**)&p_x,   g_x);
    cudaGetSymbolAddress((void**)&p_src_hi, g_src_hi);  cudaGetSymbolAddress((void**)&p_src_lo, g_src_lo);
    cudaGetSymbolAddress((void**)&p_ctx_hi, g_ctx_hi);  cudaGetSymbolAddress((void**)&p_ctx_lo, g_ctx_lo);
    cudaGetSymbolAddress((void**)&p_x_hi,   g_x_hi);    cudaGetSymbolAddress((void**)&p_x_lo,   g_x_lo);
    cudaGetSymbolAddress((void**)&p_ff1_hi, g_ff1_hi);  cudaGetSymbolAddress((void**)&p_ff1_lo, g_ff1_lo);
    cudaGetSymbolAddress((void**)&p_ipw_hi, g_ipw_hi);
    cudaGetSymbolAddress((void**)&p_outw_hi, g_outw_hi);
    cudaGetSymbolAddress((void**)&p_l1w_hi, g_l1w_hi);
    cudaGetSymbolAddress((void**)&p_l2w_hi, g_l2w_hi);

    cudaFuncSetAttribute(hmma_gemm<false,false,true,true>, cudaFuncAttributeMaxDynamicSharedMemorySize, GT_SMEM);
    cudaFuncSetAttribute(hmma_gemm<true,true,false,false>, cudaFuncAttributeMaxDynamicSharedMemorySize, GT_SMEM);
    cudaFuncSetAttribute(k_flash, cudaFuncAttributeMaxDynamicSharedMemorySize, FL_SMEM);

    auto split = [&](const float* p, __half* hi, __half* lo, size_t n) {
        int n4 = (int)(n / 4);
        k_split<<<(n4 + 255) / 256, 256>>>((const float4*)p, (__half2*)hi, (__half2*)lo, n4);
    };
    auto split_hi = [&](const float* p, __half* hi, size_t n) {
        int n4 = (int)(n / 4);
        k_split_hi<<<(n4 + 255) / 256, 256>>>((const float4*)p, (__half2*)hi, n4);
    };

    // weight + input splits (launches 1-5)
    split_hi(in_proj_w, p_ipw_hi,  (size_t)3*EMB*EMB);
    split_hi(out_w,     p_outw_hi, (size_t)EMB*EMB);
    split_hi(lin1_w,    p_l1w_hi,  (size_t)FF*EMB);
    split_hi(lin2_w,    p_l2w_hi,  (size_t)EMB*FF);
    split(src, p_src_hi, p_src_lo, (size_t)NROWS*EMB);

    // qkv projection (launch 6 — profiled by ncu -s 5 -c 1)
    hmma_gemm<false,false,true,true><<<dim3(3*EMB/128, NROWS/128), 256, GT_SMEM>>>(
        p_src_hi, p_src_lo, p_ipw_hi, in_proj_b,
        p_qkv, nullptr, nullptr, NROWS, 3*EMB, EMB);

    // positional path: pe -> L1 norm -> exact pos_sim (fp32)
    k_pe<<<(BATCH*PP*S_LEN + 255)/256, 256>>>(pos_embed, pos_w, pos_b);
    k_l1<<<(BATCH*S_LEN + 255)/256, 256>>>();
    k_possim<<<dim3(S_LEN/64, S_LEN/64, BATCH), 256>>>();

    // attention operand prep + fused flash attention
    k_prepqk<<<(BH*S_LEN*16 + 255)/256, 256>>>();
    k_prepv<<<(BH*DH*(S_LEN/4) + 255)/256, 256>>>();
    k_flash<<<dim3(S_LEN/128, BH), 256, FL_SMEM>>>();

    // output projection + LN1
    hmma_gemm<false,false,true,true><<<dim3(EMB/128, NROWS/128), 256, GT_SMEM>>>(
        p_ctx_hi, p_ctx_lo, p_outw_hi, out_b,
        p_tmp, nullptr, nullptr, NROWS, EMB, EMB);
    k_ln<true><<<NROWS, 256>>>(src, p_tmp, ln1_g, ln1_b, p_x, p_x_hi, p_x_lo);

    // FFN (lin1: A hi-only) + LN2
    hmma_gemm<true,true,false,false><<<dim3(FF/128, NROWS/128), 256, GT_SMEM>>>(
        p_x_hi, nullptr, p_l1w_hi, lin1_b,
        nullptr, p_ff1_hi, p_ff1_lo, NROWS, FF, EMB);
    hmma_gemm<false,false,true,true><<<dim3(EMB/128, NROWS/128), 256, GT_SMEM>>>(
        p_ff1_hi, p_ff1_lo, p_l2w_hi, lin2_b,
        p_tmp, nullptr, nullptr, NROWS, EMB, FF);
    k_ln<false><<<NROWS, 256>>>(p_x, p_tmp, ln2_g, ln2_b, out, nullptr, nullptr);
}

// round 16
// speedup vs baseline: 1.5232x; 1.5232x over previous
#include <cuda_runtime.h>
#include <cuda_fp16.h>
#include <math.h>
#include <stdint.h>

#define S_LEN 2048
#define BATCH 2
#define EMB   1024
#define NH    16
#define DH    64
#define PP    64
#define FF    4096
#define NROWS (S_LEN*BATCH)   // 4096
#define BH    (BATCH*NH)      // 32

// ---------------- scratch (static device allocations) ----------------
__device__ __align__(16) float g_pe[BATCH*PP*S_LEN];
__device__ __align__(16) float g_possim[(size_t)BATCH*S_LEN*S_LEN];
__device__ __align__(16) float g_qkv[(size_t)NROWS*3*EMB];
__device__ __align__(16) float g_tmp[(size_t)NROWS*EMB];
__device__ __align__(16) float g_x[(size_t)NROWS*EMB];

// fp16 split operand buffers (A-side: hi+lo; B-side weights: hi only)
__device__ __align__(16) __half g_src_hi[(size_t)NROWS*EMB],  g_src_lo[(size_t)NROWS*EMB];
__device__ __align__(16) __half g_ctx_hi[(size_t)NROWS*EMB],  g_ctx_lo[(size_t)NROWS*EMB];
__device__ __align__(16) __half g_x_hi[(size_t)NROWS*EMB],    g_x_lo[(size_t)NROWS*EMB];
__device__ __align__(16) __half g_ff1_hi[(size_t)NROWS*FF],   g_ff1_lo[(size_t)NROWS*FF];
__device__ __align__(16) __half g_ipw_hi[(size_t)3*EMB*EMB];
__device__ __align__(16) __half g_outw_hi[(size_t)EMB*EMB];
__device__ __align__(16) __half g_l1w_hi[(size_t)FF*EMB];
__device__ __align__(16) __half g_l2w_hi[(size_t)EMB*FF];

// flash-attn operands: q = 0.125*q (hi+lo), k (hi), V^T (hi), all [bh][s|d][64|t]
__device__ __align__(16) __half g_qe_hi[(size_t)BH*S_LEN*DH], g_qe_lo[(size_t)BH*S_LEN*DH];
__device__ __align__(16) __half g_ke_hi[(size_t)BH*S_LEN*DH];
__device__ __align__(16) __half g_vt_hi[(size_t)BH*DH*S_LEN];

// ---------------- helpers ----------------
__device__ __forceinline__ uint32_t smem_u32(const void* p) {
    uint32_t a;
    asm("{ .reg .u64 t; cvta.to.shared.u64 t, %1; cvt.u32.u64 %0, t; }" : "=r"(a) : "l"(p));
    return a;
}
__device__ __forceinline__ void ldm_x4(uint32_t* r, uint32_t addr) {
    asm volatile("ldmatrix.sync.aligned.m8n8.x4.shared.b16 {%0,%1,%2,%3}, [%4];"
        : "=r"(r[0]), "=r"(r[1]), "=r"(r[2]), "=r"(r[3]) : "r"(addr));
}
__device__ __forceinline__ void mma16816(float* c, const uint32_t* a, uint32_t b0, uint32_t b1) {
    asm volatile("mma.sync.aligned.m16n8k16.row.col.f32.f16.f16.f32 "
        "{%0,%1,%2,%3}, {%4,%5,%6,%7}, {%8,%9}, {%0,%1,%2,%3};"
        : "+f"(c[0]), "+f"(c[1]), "+f"(c[2]), "+f"(c[3])
        : "r"(a[0]), "r"(a[1]), "r"(a[2]), "r"(a[3]), "r"(b0), "r"(b1));
}
__device__ __forceinline__ uint32_t pack_f16x2(float a, float b) {
    uint32_t r;
    asm("cvt.rn.f16x2.f32 %0, %1, %2;" : "=r"(r) : "f"(b), "f"(a));
    return r;
}
#define CP_ASYNC16(s, g) \
    asm volatile("cp.async.cg.shared.global [%0], [%1], 16;" :: "r"(s), "l"(g))
#define CP_COMMIT() asm volatile("cp.async.commit_group;" ::: "memory")

__device__ __forceinline__ float warp_sum(float v) {
    #pragma unroll
    for (int o = 16; o; o >>= 1) v += __shfl_xor_sync(0xffffffffu, v, o);
    return v;
}

// ---------------- fp32 -> (hi, lo) fp16 split, elementwise ----------------
__global__ __launch_bounds__(256) void k_split(const float4* __restrict__ in,
                                               __half2* __restrict__ hi,
                                               __half2* __restrict__ lo, int n4) {
    int i = blockIdx.x * 256 + threadIdx.x;
    if (i >= n4) return;
    float4 v = in[i];
    __half hx = __float2half(v.x), hy = __float2half(v.y);
    __half hz = __float2half(v.z), hw = __float2half(v.w);
    __half2 h0; h0.x = hx; h0.y = hy;
    __half2 h1; h1.x = hz; h1.y = hw;
    __half2 l0; l0.x = __float2half(v.x - __half2float(hx));
                l0.y = __float2half(v.y - __half2float(hy));
    __half2 l1; l1.x = __float2half(v.z - __half2float(hz));
                l1.y = __float2half(v.w - __half2float(hw));
    hi[2*i] = h0; hi[2*i+1] = h1;
    lo[2*i] = l0; lo[2*i+1] = l1;
}

// fp32 -> fp16 hi only (weights / B-side)
__global__ __launch_bounds__(256) void k_split_hi(const float4* __restrict__ in,
                                                  __half2* __restrict__ hi, int n4) {
    int i = blockIdx.x * 256 + threadIdx.x;
    if (i >= n4) return;
    float4 v = in[i];
    __half2 h0; h0.x = __float2half(v.x); h0.y = __float2half(v.y);
    __half2 h1; h1.x = __float2half(v.z); h1.y = __float2half(v.w);
    hi[2*i] = h0; hi[2*i+1] = h1;
}

// ---------------- HMMA fp16 GEMM (A split optional), 3-stage pipeline ----------------
#define GT_TILE  10240            // 128 rows * 80 B
#define GT_STAGE (3*GT_TILE)      // Ahi, Alo, Bhi = 30720
#define GT_SMEM  (3*GT_STAGE)     // 92160 B (3 stages)

template<bool RELU, bool SPLIT, bool F32OUT, bool ALO>
__global__ __launch_bounds__(256) void hmma_gemm(
    const __half* __restrict__ Ahi, const __half* __restrict__ Alo,
    const __half* __restrict__ Bhi,
    const float* __restrict__ bias,
    float* __restrict__ C, __half* __restrict__ Chi, __half* __restrict__ Clo,
    int M, int N, int K)
{
    extern __shared__ __align__(16) char smem[];
    const uint32_t sb = smem_u32(smem);
    const int tid = threadIdx.x;
    const int lane = tid & 31, wid = tid >> 5;
    const int wm = wid >> 1, wn = wid & 1;
    const int bm = blockIdx.y * 128, bn = blockIdx.x * 128;
    const int NC = K >> 5;

    auto load_chunk = [&](int c, int buf) {
        const int k0 = c << 5;
        const uint32_t st = sb + buf * GT_STAGE;
        const __half* gp[3] = { Ahi, Alo, Bhi };
        #pragma unroll
        for (int t = 0; t < 3; ++t) {
            if (!ALO && t == 1) continue;
            const int base = (t < 2) ? bm : bn;
            const uint32_t toff = st + t * GT_TILE;
            #pragma unroll
            for (int l = 0; l < 2; ++l) {
                int i = tid + l * 256;
                int r = i >> 2, q = i & 3;
                const __half* g = gp[t] + (size_t)(base + r) * K + k0 + q * 8;
                CP_ASYNC16(toff + r * 80 + q * 16, g);
            }
        }
        CP_COMMIT();
    };

    float acc[2][8][4] = {};
    const uint32_t lm_off = (lane & 15) * 80 + ((lane >> 4) << 4);

    load_chunk(0, 0);
    if (NC > 1) load_chunk(1, 1);

    for (int c = 0; c < NC; ++c) {
        const int buf = c % 3;
        if (c + 2 < NC) {
            load_chunk(c + 2, (c + 2) % 3);
            asm volatile("cp.async.wait_group 2;" ::: "memory");
        } else if (c + 1 < NC) {
            asm volatile("cp.async.wait_group 1;" ::: "memory");
        } else {
            asm volatile("cp.async.wait_group 0;" ::: "memory");
        }
        __syncthreads();

        const uint32_t st = sb + buf * GT_STAGE;
        const uint32_t ah = st + (wm * 32) * 80 + lm_off;
        const uint32_t al = st + GT_TILE + (wm * 32) * 80 + lm_off;
        const uint32_t bb = st + 2 * GT_TILE + (wn * 64) * 80 + lm_off;
        #pragma unroll
        for (int ks = 0; ks < 2; ++ks) {
            uint32_t arh[2][4], arl[2][4], br[4][4];
            #pragma unroll
            for (int im = 0; im < 2; ++im) {
                ldm_x4(arh[im], ah + im * 16 * 80 + ks * 32);
                if (ALO) ldm_x4(arl[im], al + im * 16 * 80 + ks * 32);
            }
            #pragma unroll
            for (int ng = 0; ng < 4; ++ng)
                ldm_x4(br[ng], bb + ng * 16 * 80 + ks * 32);
            #pragma unroll
            for (int im = 0; im < 2; ++im)
                #pragma unroll
                for (int ng = 0; ng < 4; ++ng) {
                    mma16816(acc[im][2*ng+0], arh[im], br[ng][0], br[ng][2]);
                    mma16816(acc[im][2*ng+1], arh[im], br[ng][1], br[ng][3]);
                }
            if (ALO) {
                #pragma unroll
                for (int im = 0; im < 2; ++im)
                    #pragma unroll
                    for (int ng = 0; ng < 4; ++ng) {
                        mma16816(acc[im][2*ng+0], arl[im], br[ng][0], br[ng][2]);
                        mma16816(acc[im][2*ng+1], arl[im], br[ng][1], br[ng][3]);
                    }
            }
        }
        __syncthreads();
    }

    const int r0 = bm + wm * 32 + (lane >> 2);
    const int c0 = bn + wn * 64 + (lane & 3) * 2;
    #pragma unroll
    for (int im = 0; im < 2; ++im) {
        #pragma unroll
        for (int n8 = 0; n8 < 8; ++n8) {
            const int col = c0 + n8 * 8;
            const float b0 = bias[col], b1 = bias[col + 1];
            #pragma unroll
            for (int half_ = 0; half_ < 2; ++half_) {
                const int row = r0 + im * 16 + half_ * 8;
                float v0 = acc[im][n8][half_*2+0] + b0;
                float v1 = acc[im][n8][half_*2+1] + b1;
                if (RELU) { v0 = fmaxf(v0, 0.f); v1 = fmaxf(v1, 0.f); }
                if (F32OUT) {
                    *(float2*)(C + (size_t)row * N + col) = make_float2(v0, v1);
                }
                if (SPLIT) {
                    __half h0 = __float2half(v0);
                    __half h1 = __float2half(v1);
                    __half2 hh; hh.x = h0; hh.y = h1;
                    __half2 ll;
                    ll.x = __float2half(v0 - __half2float(h0));
                    ll.y = __float2half(v1 - __half2float(h1));
                    *(__half2*)(Chi + (size_t)row * N + col) = hh;
                    *(__half2*)(Clo + (size_t)row * N + col) = ll;
                }
            }
        }
    }
}

// ---------------- pe = pos_w @ pos_embed + pos_b ----------------
__global__ __launch_bounds__(256) void k_pe(const float* __restrict__ pos_embed,
                                            const float* __restrict__ pos_w,
                                            const float* __restrict__ pos_b) {
    int n = blockIdx.x * 256 + threadIdx.x;
    if (n >= BATCH*PP*S_LEN) return;
    int s = n % S_LEN;
    int q = (n / S_LEN) % PP;
    int b = n / (S_LEN * PP);
    const float* pw = pos_w + q * PP;
    const float* pem = pos_embed + (size_t)b * PP * S_LEN + s;
    float acc = pos_b[q];
    #pragma unroll 8
    for (int p = 0; p < PP; ++p) acc = fmaf(pw[p], pem[(size_t)p * S_LEN], acc);
    g_pe[n] = acc;
}

// ---------------- L1 normalize pe over q-axis ----------------
__global__ __launch_bounds__(256) void k_l1() {
    int n = blockIdx.x * 256 + threadIdx.x;
    if (n >= BATCH * S_LEN) return;
    int b = n / S_LEN, s = n % S_LEN;
    float* base = g_pe + (size_t)b * PP * S_LEN + s;
    float sum = 0.f;
    #pragma unroll 8
    for (int q = 0; q < PP; ++q) sum += fabsf(base[(size_t)q * S_LEN]);
    float inv = 1.0f / fmaxf(sum, 1e-12f);
    #pragma unroll 8
    for (int q = 0; q < PP; ++q) base[(size_t)q * S_LEN] *= inv;
}

// ---------------- pos_sim[b,s,t] = sum_q pe[b,q,s]*pe[b,q,t] (exact fp32) ----------------
__global__ __launch_bounds__(256) void k_possim() {
    __shared__ float Ps[PP][65];
    __shared__ float Pt[PP][65];
    int b = blockIdx.z;
    int t0 = blockIdx.x * 64, s0 = blockIdx.y * 64;
    int tid = threadIdx.x;
    const float* peb = g_pe + (size_t)b * PP * S_LEN;
    #pragma unroll
    for (int l = 0; l < 4; ++l) {
        int i = tid + l * 256;
        int q = i >> 4, cq = i & 15;
        float4 v = *(const float4*)(peb + (size_t)q * S_LEN + s0 + cq * 4);
        Ps[q][cq*4+0] = v.x; Ps[q][cq*4+1] = v.y; Ps[q][cq*4+2] = v.z; Ps[q][cq*4+3] = v.w;
        float4 w = *(const float4*)(peb + (size_t)q * S_LEN + t0 + cq * 4);
        Pt[q][cq*4+0] = w.x; Pt[q][cq*4+1] = w.y; Pt[q][cq*4+2] = w.z; Pt[q][cq*4+3] = w.w;
    }
    __syncthreads();
    int ty = tid / 16, tx = tid % 16;
    float acc[4][4] = {};
    #pragma unroll 8
    for (int q = 0; q < PP; ++q) {
        float a[4], c[4];
        #pragma unroll
        for (int i = 0; i < 4; ++i) a[i] = Ps[q][ty*4+i];
        #pragma unroll
        for (int j = 0; j < 4; ++j) c[j] = Pt[q][tx*4+j];
        #pragma unroll
        for (int i = 0; i < 4; ++i)
            #pragma unroll
            for (int j = 0; j < 4; ++j) acc[i][j] = fmaf(a[i], c[j], acc[i][j]);
    }
    #pragma unroll
    for (int i = 0; i < 4; ++i) {
        int sr = s0 + ty*4 + i;
        float4 o = make_float4(acc[i][0], acc[i][1], acc[i][2], acc[i][3]);
        *(float4*)(g_possim + ((size_t)b * S_LEN + sr) * S_LEN + t0 + tx*4) = o;
    }
}

// ---------------- build q (hi/lo, pre-scaled) and k (hi), [bh][s][64] ----------------
__global__ __launch_bounds__(256) void k_prepqk() {
    int idx = blockIdx.x * 256 + threadIdx.x;          // over BH*S*16
    if (idx >= BH * S_LEN * 16) return;
    int j4 = (idx & 15) * 4;
    int s  = (idx >> 4) & (S_LEN - 1);
    int bh = idx >> 15;
    int b = bh / NH, h = bh % NH;
    size_t qbase = ((size_t)s * BATCH + b) * (3*EMB) + h * DH + j4;
    size_t obase = ((size_t)bh * S_LEN + s) * DH + j4;
    #pragma unroll
    for (int u = 0; u < 4; ++u) {
        float qv = 0.125f * g_qkv[qbase + u];
        float kv = g_qkv[qbase + EMB + u];
        __half qh = __float2half(qv);
        g_qe_hi[obase + u] = qh;
        g_qe_lo[obase + u] = __float2half(qv - __half2float(qh));
        g_ke_hi[obase + u] = __float2half(kv);
    }
}

// ---------------- build V^T [bh][d][t] (hi) ----------------
__global__ __launch_bounds__(256) void k_prepv() {
    int idx = blockIdx.x * 256 + threadIdx.x;          // over BH*64*(S/4)
    if (idx >= BH * DH * (S_LEN/4)) return;
    int t4 = (idx & (S_LEN/4 - 1)) * 4;
    int d  = (idx >> 9) & 63;
    int bh = idx >> 15;
    int b = bh / NH, h = bh % NH;
    size_t obase = ((size_t)bh * DH + d) * S_LEN + t4;
    #pragma unroll
    for (int u = 0; u < 4; ++u) {
        int t = t4 + u;
        float v = g_qkv[((size_t)t * BATCH + b) * (3*EMB) + 2*EMB + h*DH + d];
        g_vt_hi[obase + u] = __float2half(v);
    }
}

// ---------------- fused flash attention (K=64, pos_sim added from gmem after QK) ----------------
#define FL_KV    20480
#define FL_VHI   10240
#define FL_QOFF  (2*FL_KV)         // 40960
#define FL_QLO   20480
#define FL_SMEM  (FL_QOFF + 40960) // 81920

__global__ __launch_bounds__(256, 1) void k_flash() {
    extern __shared__ __align__(16) char smem[];
    const uint32_t sb = smem_u32(smem);
    const int tid = threadIdx.x, lane = tid & 31, w = tid >> 5;
    const int s0 = blockIdx.x * 128;
    const int bh = blockIdx.y;
    const int b = bh / NH, h = bh % NH;
    const uint32_t lm = (lane & 15) * 80 + ((lane >> 4) << 4);

    // ---- async load q tile (128 rows x 64 K, hi+lo) ----
    const __half* qhg = g_qe_hi + ((size_t)bh * S_LEN + s0) * DH;
    const __half* qlg = g_qe_lo + ((size_t)bh * S_LEN + s0) * DH;
    #pragma unroll
    for (int l = 0; l < 4; ++l) {
        int i = tid + l * 256;            // [0,1024): r=i/8, q=i%8
        int r = i >> 3, q = i & 7;
        int kc = q >> 2, qq = q & 3;
        CP_ASYNC16(sb + FL_QOFF + kc*10240 + r*80 + qq*16, qhg + (size_t)r*DH + kc*32 + qq*8);
        CP_ASYNC16(sb + FL_QOFF + FL_QLO + kc*10240 + r*80 + qq*16, qlg + (size_t)r*DH + kc*32 + qq*8);
    }
    CP_COMMIT();

    // kv chunk loader: 64 t-rows of k hi (K=64) + 64 d-rows of V^T hi (t-chunk 64)
    auto load_kv = [&](int c, int buf) {
        const uint32_t kb = sb + buf * FL_KV;
        const __half* khg = g_ke_hi + ((size_t)bh * S_LEN + c*64) * DH;
        #pragma unroll
        for (int l = 0; l < 2; ++l) {
            int i = tid + l * 256;        // [0,512): r=i/8, q=i%8
            int r = i >> 3, q = i & 7;
            int kc = q >> 2, qq = q & 3;
            CP_ASYNC16(kb + kc*5120 + r*80 + qq*16, khg + (size_t)r*DH + kc*32 + qq*8);
        }
        const __half* vhg = g_vt_hi + (size_t)bh * DH * S_LEN + c*64;
        #pragma unroll
        for (int l = 0; l < 2; ++l) {
            int i = tid + l * 256;        // [0,512): r=i/8, q=i%8
            int r = i >> 3, q = i & 7;
            int kc = q >> 2, qq = q & 3;
            CP_ASYNC16(kb + FL_VHI + kc*5120 + r*80 + qq*16, vhg + (size_t)r*S_LEN + kc*32 + qq*8);
        }
        CP_COMMIT();
    };

    load_kv(0, 0);
    asm volatile("cp.async.wait_group 0;" ::: "memory");
    __syncthreads();

    // ---- extract q A-fragments into registers (4 k16-slices, hi+lo) ----
    uint32_t aqh[4][4], aql[4][4];
    #pragma unroll
    for (int ks4 = 0; ks4 < 4; ++ks4) {
        int kc = ks4 >> 1, ks = ks4 & 1;
        ldm_x4(aqh[ks4], sb + FL_QOFF + kc*10240 + (w*16)*80 + lm + ks*32);
        ldm_x4(aql[ks4], sb + FL_QOFF + FL_QLO + kc*10240 + (w*16)*80 + lm + ks*32);
    }

    // pos_sim row pointers for this thread's two C-fragment rows
    const float* pr0 = g_possim + ((size_t)b * S_LEN + (s0 + w*16 + (lane >> 2))) * S_LEN + (lane & 3) * 2;
    const float* pr1 = pr0 + (size_t)8 * S_LEN;

    float octx[8][4] = {};
    float m0 = -1e30f, m1 = -1e30f, l0 = 0.f, l1 = 0.f;
    const int NC = S_LEN / 64;

    for (int c = 0; c < NC; ++c) {
        const int buf = c & 1;
        if (c + 1 < NC) {
            load_kv(c + 1, buf ^ 1);
            asm volatile("cp.async.wait_group 1;" ::: "memory");
        } else {
            asm volatile("cp.async.wait_group 0;" ::: "memory");
        }
        __syncthreads();
        const uint32_t kb = sb + buf * FL_KV;

        // ---- QK: P[16 x 64] = q * k^T  (2-pass split on q, K=64) ----
        float ps[8][4] = {};
        #pragma unroll
        for (int ks4 = 0; ks4 < 4; ++ks4) {
            int kc = ks4 >> 1, ks = ks4 & 1;
            uint32_t bh4[4][4];
            #pragma unroll
            for (int ng = 0; ng < 4; ++ng)
                ldm_x4(bh4[ng], kb + kc*5120 + (ng*16)*80 + lm + ks*32);
            #pragma unroll
            for (int ng = 0; ng < 4; ++ng) {
                mma16816(ps[2*ng],   aqh[ks4], bh4[ng][0], bh4[ng][2]);
                mma16816(ps[2*ng+1], aqh[ks4], bh4[ng][1], bh4[ng][3]);
                mma16816(ps[2*ng],   aql[ks4], bh4[ng][0], bh4[ng][2]);
                mma16816(ps[2*ng+1], aql[ks4], bh4[ng][1], bh4[ng][3]);
            }
        }

        // ---- add pos_sim (exact fp32, from L2-resident gmem) ----
        {
            const float* p0 = pr0 + c * 64;
            const float* p1 = pr1 + c * 64;
            #pragma unroll
            for (int ng = 0; ng < 8; ++ng) {
                float2 a0 = *(const float2*)(p0 + ng * 8);
                float2 a1 = *(const float2*)(p1 + ng * 8);
                ps[ng][0] += a0.x; ps[ng][1] += a0.y;
                ps[ng][2] += a1.x; ps[ng][3] += a1.y;
            }
        }

        // ---- online softmax (rows: half0 = lane/4, half1 = +8) ----
        float mx0 = -1e30f, mx1 = -1e30f;
        #pragma unroll
        for (int ng = 0; ng < 8; ++ng) {
            mx0 = fmaxf(mx0, fmaxf(ps[ng][0], ps[ng][1]));
            mx1 = fmaxf(mx1, fmaxf(ps[ng][2], ps[ng][3]));
        }
        mx0 = fmaxf(mx0, __shfl_xor_sync(0xffffffffu, mx0, 1));
        mx0 = fmaxf(mx0, __shfl_xor_sync(0xffffffffu, mx0, 2));
        mx1 = fmaxf(mx1, __shfl_xor_sync(0xffffffffu, mx1, 1));
        mx1 = fmaxf(mx1, __shfl_xor_sync(0xffffffffu, mx1, 2));
        float mn0 = fmaxf(m0, mx0), mn1 = fmaxf(m1, mx1);
        float sc0 = __expf(m0 - mn0), sc1 = __expf(m1 - mn1);
        m0 = mn0; m1 = mn1;
        l0 *= sc0; l1 *= sc1;
        #pragma unroll
        for (int ng = 0; ng < 8; ++ng) {
            octx[ng][0] *= sc0; octx[ng][1] *= sc0;
            octx[ng][2] *= sc1; octx[ng][3] *= sc1;
        }
        float rs0 = 0.f, rs1 = 0.f;
        #pragma unroll
        for (int ng = 0; ng < 8; ++ng) {
            ps[ng][0] = __expf(ps[ng][0] - mn0);
            ps[ng][1] = __expf(ps[ng][1] - mn0);
            ps[ng][2] = __expf(ps[ng][2] - mn1);
            ps[ng][3] = __expf(ps[ng][3] - mn1);
            rs0 += ps[ng][0] + ps[ng][1];
            rs1 += ps[ng][2] + ps[ng][3];
        }
        rs0 += __shfl_xor_sync(0xffffffffu, rs0, 1);
        rs0 += __shfl_xor_sync(0xffffffffu, rs0, 2);
        rs1 += __shfl_xor_sync(0xffffffffu, rs1, 1);
        rs1 += __shfl_xor_sync(0xffffffffu, rs1, 2);
        l0 += rs0; l1 += rs1;

        // ---- register C-frag -> A-frag conversion (P hi only) ----
        uint32_t aph[4][4];
        #pragma unroll
        for (int kj = 0; kj < 4; ++kj) {
            #pragma unroll
            for (int q = 0; q < 4; ++q) {
                int nb = 2*kj + (q >> 1);
                float e0 = ps[nb][(q & 1) * 2 + 0];
                float e1 = ps[nb][(q & 1) * 2 + 1];
                aph[kj][q] = pack_f16x2(e0, e1);
            }
        }

        // ---- PV: ctx += P * V  (single-pass), B = V^T hi ----
        #pragma unroll
        for (int kj = 0; kj < 4; ++kj) {
            int kc = kj >> 1, ks = kj & 1;
            uint32_t vh4[4][4];
            #pragma unroll
            for (int ng = 0; ng < 4; ++ng)
                ldm_x4(vh4[ng], kb + FL_VHI + kc*5120 + (ng*16)*80 + lm + ks*32);
            #pragma unroll
            for (int ng = 0; ng < 4; ++ng) {
                mma16816(octx[2*ng],   aph[kj], vh4[ng][0], vh4[ng][2]);
                mma16816(octx[2*ng+1], aph[kj], vh4[ng][1], vh4[ng][3]);
            }
        }
        __syncthreads();
    }

    // ---- epilogue: normalize, write ctx hi/lo (layout [(s*B+b)*E + h*64 + d]) ----
    float i0 = 1.f / l0, i1 = 1.f / l1;
    const int g = lane >> 2;
    #pragma unroll
    for (int half_ = 0; half_ < 2; ++half_) {
        const int s = s0 + w * 16 + g + half_ * 8;
        const float ih = half_ ? i1 : i0;
        size_t base = ((size_t)s * BATCH + b) * EMB + h * DH;
        #pragma unroll
        for (int ng = 0; ng < 8; ++ng) {
            int col = ng * 8 + (lane & 3) * 2;
            float v0 = octx[ng][half_*2+0] * ih;
            float v1 = octx[ng][half_*2+1] * ih;
            __half h0 = __float2half(v0);
            __half h1 = __float2half(v1);
            __half2 hh; hh.x = h0; hh.y = h1;
            __half2 ll;
            ll.x = __float2half(v0 - __half2float(h0));
            ll.y = __float2half(v1 - __half2float(h1));
            *(__half2*)(g_ctx_hi + base + col) = hh;
            *(__half2*)(g_ctx_lo + base + col) = ll;
        }
    }
}

// ---------------- out = LayerNorm(A + B), optional fp16 split emission ----------------
template<bool SPLIT>
__global__ __launch_bounds__(256) void k_ln(const float* __restrict__ A,
                                            const float* __restrict__ Bv,
                                            const float* __restrict__ gam,
                                            const float* __restrict__ bet,
                                            float* __restrict__ out,
                                            __half* __restrict__ ohi,
                                            __half* __restrict__ olo) {
    __shared__ float red[8];
    size_t row = blockIdx.x;
    const float* a = A + row * EMB;
    const float* b = Bv + row * EMB;
    int tid = threadIdx.x;
    int lane = tid & 31, wid = tid >> 5;
    float v[4];
    float sum = 0.f;
    #pragma unroll
    for (int i = 0; i < 4; ++i) { v[i] = a[tid + i*256] + b[tid + i*256]; sum += v[i]; }
    sum = warp_sum(sum);
    if (lane == 0) red[wid] = sum;
    __syncthreads();
    if (wid == 0) {
        float t = (lane < 8) ? red[lane] : 0.f;
        t = warp_sum(t);
        if (lane == 0) red[0] = t;
    }
    __syncthreads();
    float mu = red[0] * (1.0f / EMB);
    __syncthreads();
    float sq = 0.f;
    #pragma unroll
    for (int i = 0; i < 4; ++i) { float d = v[i] - mu; sq += d * d; }
    sq = warp_sum(sq);
    if (lane == 0) red[wid] = sq;
    __syncthreads();
    if (wid == 0) {
        float t = (lane < 8) ? red[lane] : 0.f;
        t = warp_sum(t);
        if (lane == 0) red[0] = t;
    }
    __syncthreads();
    float inv = rsqrtf(red[0] * (1.0f / EMB) + 1e-5f);
    #pragma unroll
    for (int i = 0; i < 4; ++i) {
        int c = tid + i*256;
        float o = (v[i] - mu) * inv * gam[c] + bet[c];
        out[row * EMB + c] = o;
        if (SPLIT) {
            __half h = __float2half(o);
            ohi[row * EMB + c] = h;
            olo[row * EMB + c] = __float2half(o - __half2float(h));
        }
    }
}

// ---------------- launch ----------------
extern "C" void kernel_launch(void* const* d_in, const int* in_sizes, int n_in,
                              void* d_out, int out_size) {
    const float* src       = (const float*)d_in[0];
    const float* pos_embed = (const float*)d_in[1];
    const float* in_proj_w = (const float*)d_in[2];
    const float* in_proj_b = (const float*)d_in[3];
    const float* out_w     = (const float*)d_in[4];
    const float* out_b     = (const float*)d_in[5];
    const float* lin1_w    = (const float*)d_in[6];
    const float* lin1_b    = (const float*)d_in[7];
    const float* lin2_w    = (const float*)d_in[8];
    const float* lin2_b    = (const float*)d_in[9];
    const float* ln1_g     = (const float*)d_in[10];
    const float* ln1_b     = (const float*)d_in[11];
    const float* ln2_g     = (const float*)d_in[12];
    const float* ln2_b     = (const float*)d_in[13];
    const float* pos_w     = (const float*)d_in[14];
    const float* pos_b     = (const float*)d_in[15];
    float* out = (float*)d_out;

    float *p_qkv, *p_tmp, *p_x;
    __half *p_src_hi, *p_src_lo, *p_ctx_hi, *p_ctx_lo, *p_x_hi, *p_x_lo;
    __half *p_ff1_hi, *p_ff1_lo;
    __half *p_ipw_hi, *p_outw_hi, *p_l1w_hi, *p_l2w_hi;
    cudaGetSymbolAddress((void**)&p_qkv, g_qkv);
    cudaGetSymbolAddress((void**)&p_tmp, g_tmp);
    cudaGetSymbolAddress((void**)&p_x,   g_x);
    cudaGetSymbolAddress((void**)&p_src_hi, g_src_hi);  cudaGetSymbolAddress((void**)&p_src_lo, g_src_lo);
    cudaGetSymbolAddress((void**)&p_ctx_hi, g_ctx_hi);  cudaGetSymbolAddress((void**)&p_ctx_lo, g_ctx_lo);
    cudaGetSymbolAddress((void**)&p_x_hi,   g_x_hi);    cudaGetSymbolAddress((void**)&p_x_lo,   g_x_lo);
    cudaGetSymbolAddress((void**)&p_ff1_hi, g_ff1_hi);  cudaGetSymbolAddress((void**)&p_ff1_lo, g_ff1_lo);
    cudaGetSymbolAddress((void**)&p_ipw_hi, g_ipw_hi);
    cudaGetSymbolAddress((void**)&p_outw_hi, g_outw_hi);
    cudaGetSymbolAddress((void**)&p_l1w_hi, g_l1w_hi);
    cudaGetSymbolAddress((void**)&p_l2w_hi, g_l2w_hi);

    cudaFuncSetAttribute(hmma_gemm<false,false,true,true>, cudaFuncAttributeMaxDynamicSharedMemorySize, GT_SMEM);
    cudaFuncSetAttribute(hmma_gemm<true,true,false,false>, cudaFuncAttributeMaxDynamicSharedMemorySize, GT_SMEM);
    cudaFuncSetAttribute(k_flash, cudaFuncAttributeMaxDynamicSharedMemorySize, FL_SMEM);

    auto split = [&](const float* p, __half* hi, __half* lo, size_t n) {
        int n4 = (int)(n / 4);
        k_split<<<(n4 + 255) / 256, 256>>>((const float4*)p, (__half2*)hi, (__half2*)lo, n4);
    };
    auto split_hi = [&](const float* p, __half* hi, size_t n) {
        int n4 = (int)(n / 4);
        k_split_hi<<<(n4 + 255) / 256, 256>>>((const float4*)p, (__half2*)hi, n4);
    };

    // weight + input splits (launches 1-5)
    split_hi(in_proj_w, p_ipw_hi,  (size_t)3*EMB*EMB);
    split_hi(out_w,     p_outw_hi, (size_t)EMB*EMB);
    split_hi(lin1_w,    p_l1w_hi,  (size_t)FF*EMB);
    split_hi(lin2_w,    p_l2w_hi,  (size_t)EMB*FF);
    split(src, p_src_hi, p_src_lo, (size_t)NROWS*EMB);

    // qkv projection (launch 6 — profiled by ncu -s 5 -c 1)
    hmma_gemm<false,false,true,true><<<dim3(3*EMB/128, NROWS/128), 256, GT_SMEM>>>(
        p_src_hi, p_src_lo, p_ipw_hi, in_proj_b,
        p_qkv, nullptr, nullptr, NROWS, 3*EMB, EMB);

    // positional path: pe -> L1 norm -> exact pos_sim (fp32)
    k_pe<<<(BATCH*PP*S_LEN + 255)/256, 256>>>(pos_embed, pos_w, pos_b);
    k_l1<<<(BATCH*S_LEN + 255)/256, 256>>>();
    k_possim<<<dim3(S_LEN/64, S_LEN/64, BATCH), 256>>>();

    // attention operand prep + fused flash attention
    k_prepqk<<<(BH*S_LEN*16 + 255)/256, 256>>>();
    k_prepv<<<(BH*DH*(S_LEN/4) + 255)/256, 256>>>();
    k_flash<<<dim3(S_LEN/128, BH), 256, FL_SMEM>>>();

    // output projection + LN1
    hmma_gemm<false,false,true,true><<<dim3(EMB/128, NROWS/128), 256, GT_SMEM>>>(
        p_ctx_hi, p_ctx_lo, p_outw_hi, out_b,
        p_tmp, nullptr, nullptr, NROWS, EMB, EMB);
    k_ln<true><<<NROWS, 256>>>(src, p_tmp, ln1_g, ln1_b, p_x, p_x_hi, p_x_lo);

    // FFN (lin1: A hi-only) + LN2
    hmma_gemm<true,true,false,false><<<dim3(FF/128, NROWS/128), 256, GT_SMEM>>>(
        p_x_hi, nullptr, p_l1w_hi, lin1_b,
        nullptr, p_ff1_hi, p_ff1_lo, NROWS, FF, EMB);
    hmma_gemm<false,false,true,true><<<dim3(EMB/128, NROWS/128), 256, GT_SMEM>>>(
        p_ff1_hi, p_ff1_lo, p_l2w_hi, lin2_b,
        p_tmp, nullptr, nullptr, NROWS, EMB, FF);
    k_ln<false><<<NROWS, 256>>>(p_x, p_tmp, ln2_g, ln2_b, out, nullptr, nullptr);
}

// round 17
// speedup vs baseline: 1.9737x; 1.2957x over previous
#include <cuda_runtime.h>
#include <cuda_fp16.h>
#include <math.h>
#include <stdint.h>

#define S_LEN 2048
#define BATCH 2
#define EMB   1024
#define NH    16
#define DH    64
#define PP    64
#define FF    4096
#define NROWS (S_LEN*BATCH)   // 4096
#define BH    (BATCH*NH)      // 32

// ---------------- scratch (static device allocations) ----------------
__device__ __align__(16) float g_pe[BATCH*PP*S_LEN];
__device__ __align__(16) float g_possim[(size_t)BATCH*S_LEN*S_LEN];
__device__ __align__(16) float g_qkv[(size_t)NROWS*3*EMB];
__device__ __align__(16) float g_tmp[(size_t)NROWS*EMB];
__device__ __align__(16) float g_x[(size_t)NROWS*EMB];

// fp16 operand buffers (A-side and B-side: hi only)
__device__ __align__(16) __half g_src_hi[(size_t)NROWS*EMB];
__device__ __align__(16) __half g_ctx_hi[(size_t)NROWS*EMB];
__device__ __align__(16) __half g_x_hi[(size_t)NROWS*EMB];
__device__ __align__(16) __half g_ff1_hi[(size_t)NROWS*FF];
__device__ __align__(16) __half g_ipw_hi[(size_t)3*EMB*EMB];
__device__ __align__(16) __half g_outw_hi[(size_t)EMB*EMB];
__device__ __align__(16) __half g_l1w_hi[(size_t)FF*EMB];
__device__ __align__(16) __half g_l2w_hi[(size_t)EMB*FF];

// flash-attn operands: q = 0.125*q (hi+lo), k (hi), V^T (hi), all [bh][s|d][64|t]
__device__ __align__(16) __half g_qe_hi[(size_t)BH*S_LEN*DH], g_qe_lo[(size_t)BH*S_LEN*DH];
__device__ __align__(16) __half g_ke_hi[(size_t)BH*S_LEN*DH];
__device__ __align__(16) __half g_vt_hi[(size_t)BH*DH*S_LEN];

// ---------------- helpers ----------------
__device__ __forceinline__ uint32_t smem_u32(const void* p) {
    uint32_t a;
    asm("{ .reg .u64 t; cvta.to.shared.u64 t, %1; cvt.u32.u64 %0, t; }" : "=r"(a) : "l"(p));
    return a;
}
__device__ __forceinline__ void ldm_x4(uint32_t* r, uint32_t addr) {
    asm volatile("ldmatrix.sync.aligned.m8n8.x4.shared.b16 {%0,%1,%2,%3}, [%4];"
        : "=r"(r[0]), "=r"(r[1]), "=r"(r[2]), "=r"(r[3]) : "r"(addr));
}
__device__ __forceinline__ void mma16816(float* c, const uint32_t* a, uint32_t b0, uint32_t b1) {
    asm volatile("mma.sync.aligned.m16n8k16.row.col.f32.f16.f16.f32 "
        "{%0,%1,%2,%3}, {%4,%5,%6,%7}, {%8,%9}, {%0,%1,%2,%3};"
        : "+f"(c[0]), "+f"(c[1]), "+f"(c[2]), "+f"(c[3])
        : "r"(a[0]), "r"(a[1]), "r"(a[2]), "r"(a[3]), "r"(b0), "r"(b1));
}
__device__ __forceinline__ uint32_t pack_f16x2(float a, float b) {
    uint32_t r;
    asm("cvt.rn.f16x2.f32 %0, %1, %2;" : "=r"(r) : "f"(b), "f"(a));
    return r;
}
#define CP_ASYNC16(s, g) \
    asm volatile("cp.async.cg.shared.global [%0], [%1], 16;" :: "r"(s), "l"(g))
#define CP_COMMIT() asm volatile("cp.async.commit_group;" ::: "memory")

__device__ __forceinline__ float warp_sum(float v) {
    #pragma unroll
    for (int o = 16; o; o >>= 1) v += __shfl_xor_sync(0xffffffffu, v, o);
    return v;
}

// fp32 -> fp16 hi only
__global__ __launch_bounds__(256) void k_split_hi(const float4* __restrict__ in,
                                                  __half2* __restrict__ hi, int n4) {
    int i = blockIdx.x * 256 + threadIdx.x;
    if (i >= n4) return;
    float4 v = in[i];
    __half2 h0; h0.x = __float2half(v.x); h0.y = __float2half(v.y);
    __half2 h1; h1.x = __float2half(v.z); h1.y = __float2half(v.w);
    hi[2*i] = h0; hi[2*i+1] = h1;
}

// ---------------- HMMA fp16 GEMM (hi-only, single pass), 3-stage pipeline ----------------
#define GT_TILE  10240            // 128 rows * 80 B
#define GT_STAGE (2*GT_TILE)      // Ahi, Bhi = 20480
#define GT_SMEM  (3*GT_STAGE)     // 61440 B (3 stages)

template<bool RELU, bool SPLIT, bool F32OUT>
__global__ __launch_bounds__(256) void hmma_gemm(
    const __half* __restrict__ Ahi,
    const __half* __restrict__ Bhi,
    const float* __restrict__ bias,
    float* __restrict__ C, __half* __restrict__ Chi,
    int M, int N, int K)
{
    extern __shared__ __align__(16) char smem[];
    const uint32_t sb = smem_u32(smem);
    const int tid = threadIdx.x;
    const int lane = tid & 31, wid = tid >> 5;
    const int wm = wid >> 1, wn = wid & 1;
    const int bm = blockIdx.y * 128, bn = blockIdx.x * 128;
    const int NC = K >> 5;

    auto load_chunk = [&](int c, int buf) {
        const int k0 = c << 5;
        const uint32_t st = sb + buf * GT_STAGE;
        const __half* gp[2] = { Ahi, Bhi };
        #pragma unroll
        for (int t = 0; t < 2; ++t) {
            const int base = (t == 0) ? bm : bn;
            const uint32_t toff = st + t * GT_TILE;
            #pragma unroll
            for (int l = 0; l < 2; ++l) {
                int i = tid + l * 256;
                int r = i >> 2, q = i & 3;
                const __half* g = gp[t] + (size_t)(base + r) * K + k0 + q * 8;
                CP_ASYNC16(toff + r * 80 + q * 16, g);
            }
        }
        CP_COMMIT();
    };

    float acc[2][8][4] = {};
    const uint32_t lm_off = (lane & 15) * 80 + ((lane >> 4) << 4);

    load_chunk(0, 0);
    if (NC > 1) load_chunk(1, 1);

    for (int c = 0; c < NC; ++c) {
        const int buf = c % 3;
        if (c + 2 < NC) {
            load_chunk(c + 2, (c + 2) % 3);
            asm volatile("cp.async.wait_group 2;" ::: "memory");
        } else if (c + 1 < NC) {
            asm volatile("cp.async.wait_group 1;" ::: "memory");
        } else {
            asm volatile("cp.async.wait_group 0;" ::: "memory");
        }
        __syncthreads();

        const uint32_t st = sb + buf * GT_STAGE;
        const uint32_t ah = st + (wm * 32) * 80 + lm_off;
        const uint32_t bb = st + GT_TILE + (wn * 64) * 80 + lm_off;
        #pragma unroll
        for (int ks = 0; ks < 2; ++ks) {
            uint32_t arh[2][4], br[4][4];
            #pragma unroll
            for (int im = 0; im < 2; ++im)
                ldm_x4(arh[im], ah + im * 16 * 80 + ks * 32);
            #pragma unroll
            for (int ng = 0; ng < 4; ++ng)
                ldm_x4(br[ng], bb + ng * 16 * 80 + ks * 32);
            #pragma unroll
            for (int im = 0; im < 2; ++im)
                #pragma unroll
                for (int ng = 0; ng < 4; ++ng) {
                    mma16816(acc[im][2*ng+0], arh[im], br[ng][0], br[ng][2]);
                    mma16816(acc[im][2*ng+1], arh[im], br[ng][1], br[ng][3]);
                }
        }
        __syncthreads();
    }

    const int r0 = bm + wm * 32 + (lane >> 2);
    const int c0 = bn + wn * 64 + (lane & 3) * 2;
    #pragma unroll
    for (int im = 0; im < 2; ++im) {
        #pragma unroll
        for (int n8 = 0; n8 < 8; ++n8) {
            const int col = c0 + n8 * 8;
            const float b0 = bias[col], b1 = bias[col + 1];
            #pragma unroll
            for (int half_ = 0; half_ < 2; ++half_) {
                const int row = r0 + im * 16 + half_ * 8;
                float v0 = acc[im][n8][half_*2+0] + b0;
                float v1 = acc[im][n8][half_*2+1] + b1;
                if (RELU) { v0 = fmaxf(v0, 0.f); v1 = fmaxf(v1, 0.f); }
                if (F32OUT) {
                    *(float2*)(C + (size_t)row * N + col) = make_float2(v0, v1);
                }
                if (SPLIT) {
                    __half2 hh; hh.x = __float2half(v0); hh.y = __float2half(v1);
                    *(__half2*)(Chi + (size_t)row * N + col) = hh;
                }
            }
        }
    }
}

// ---------------- pe = pos_w @ pos_embed + pos_b ----------------
__global__ __launch_bounds__(256) void k_pe(const float* __restrict__ pos_embed,
                                            const float* __restrict__ pos_w,
                                            const float* __restrict__ pos_b) {
    int n = blockIdx.x * 256 + threadIdx.x;
    if (n >= BATCH*PP*S_LEN) return;
    int s = n % S_LEN;
    int q = (n / S_LEN) % PP;
    int b = n / (S_LEN * PP);
    const float* pw = pos_w + q * PP;
    const float* pem = pos_embed + (size_t)b * PP * S_LEN + s;
    float acc = pos_b[q];
    #pragma unroll 8
    for (int p = 0; p < PP; ++p) acc = fmaf(pw[p], pem[(size_t)p * S_LEN], acc);
    g_pe[n] = acc;
}

// ---------------- L1 normalize pe over q-axis ----------------
__global__ __launch_bounds__(256) void k_l1() {
    int n = blockIdx.x * 256 + threadIdx.x;
    if (n >= BATCH * S_LEN) return;
    int b = n / S_LEN, s = n % S_LEN;
    float* base = g_pe + (size_t)b * PP * S_LEN + s;
    float sum = 0.f;
    #pragma unroll 8
    for (int q = 0; q < PP; ++q) sum += fabsf(base[(size_t)q * S_LEN]);
    float inv = 1.0f / fmaxf(sum, 1e-12f);
    #pragma unroll 8
    for (int q = 0; q < PP; ++q) base[(size_t)q * S_LEN] *= inv;
}

// ---------------- pos_sim[b,s,t] = sum_q pe[b,q,s]*pe[b,q,t] (exact fp32) ----------------
__global__ __launch_bounds__(256) void k_possim() {
    __shared__ float Ps[PP][65];
    __shared__ float Pt[PP][65];
    int b = blockIdx.z;
    int t0 = blockIdx.x * 64, s0 = blockIdx.y * 64;
    int tid = threadIdx.x;
    const float* peb = g_pe + (size_t)b * PP * S_LEN;
    #pragma unroll
    for (int l = 0; l < 4; ++l) {
        int i = tid + l * 256;
        int q = i >> 4, cq = i & 15;
        float4 v = *(const float4*)(peb + (size_t)q * S_LEN + s0 + cq * 4);
        Ps[q][cq*4+0] = v.x; Ps[q][cq*4+1] = v.y; Ps[q][cq*4+2] = v.z; Ps[q][cq*4+3] = v.w;
        float4 w = *(const float4*)(peb + (size_t)q * S_LEN + t0 + cq * 4);
        Pt[q][cq*4+0] = w.x; Pt[q][cq*4+1] = w.y; Pt[q][cq*4+2] = w.z; Pt[q][cq*4+3] = w.w;
    }
    __syncthreads();
    int ty = tid / 16, tx = tid % 16;
    float acc[4][4] = {};
    #pragma unroll 8
    for (int q = 0; q < PP; ++q) {
        float a[4], c[4];
        #pragma unroll
        for (int i = 0; i < 4; ++i) a[i] = Ps[q][ty*4+i];
        #pragma unroll
        for (int j = 0; j < 4; ++j) c[j] = Pt[q][tx*4+j];
        #pragma unroll
        for (int i = 0; i < 4; ++i)
            #pragma unroll
            for (int j = 0; j < 4; ++j) acc[i][j] = fmaf(a[i], c[j], acc[i][j]);
    }
    #pragma unroll
    for (int i = 0; i < 4; ++i) {
        int sr = s0 + ty*4 + i;
        float4 o = make_float4(acc[i][0], acc[i][1], acc[i][2], acc[i][3]);
        *(float4*)(g_possim + ((size_t)b * S_LEN + sr) * S_LEN + t0 + tx*4) = o;
    }
}

// ---------------- build q (hi/lo, pre-scaled) and k (hi), [bh][s][64] ----------------
__global__ __launch_bounds__(256) void k_prepqk() {
    int idx = blockIdx.x * 256 + threadIdx.x;          // over BH*S*16
    if (idx >= BH * S_LEN * 16) return;
    int j4 = (idx & 15) * 4;
    int s  = (idx >> 4) & (S_LEN - 1);
    int bh = idx >> 15;
    int b = bh / NH, h = bh % NH;
    size_t qbase = ((size_t)s * BATCH + b) * (3*EMB) + h * DH + j4;
    size_t obase = ((size_t)bh * S_LEN + s) * DH + j4;
    #pragma unroll
    for (int u = 0; u < 4; ++u) {
        float qv = 0.125f * g_qkv[qbase + u];
        float kv = g_qkv[qbase + EMB + u];
        __half qh = __float2half(qv);
        g_qe_hi[obase + u] = qh;
        g_qe_lo[obase + u] = __float2half(qv - __half2float(qh));
        g_ke_hi[obase + u] = __float2half(kv);
    }
}

// ---------------- build V^T [bh][d][t] (hi) ----------------
__global__ __launch_bounds__(256) void k_prepv() {
    int idx = blockIdx.x * 256 + threadIdx.x;          // over BH*64*(S/4)
    if (idx >= BH * DH * (S_LEN/4)) return;
    int t4 = (idx & (S_LEN/4 - 1)) * 4;
    int d  = (idx >> 9) & 63;
    int bh = idx >> 15;
    int b = bh / NH, h = bh % NH;
    size_t obase = ((size_t)bh * DH + d) * S_LEN + t4;
    #pragma unroll
    for (int u = 0; u < 4; ++u) {
        int t = t4 + u;
        float v = g_qkv[((size_t)t * BATCH + b) * (3*EMB) + 2*EMB + h*DH + d];
        g_vt_hi[obase + u] = __float2half(v);
    }
}

// ---------------- fused flash attention (K=64, pos_sim added from gmem after QK) ----------------
#define FL_KV    20480
#define FL_VHI   10240
#define FL_QOFF  (2*FL_KV)         // 40960
#define FL_QLO   20480
#define FL_SMEM  (FL_QOFF + 40960) // 81920

__global__ __launch_bounds__(256, 1) void k_flash() {
    extern __shared__ __align__(16) char smem[];
    const uint32_t sb = smem_u32(smem);
    const int tid = threadIdx.x, lane = tid & 31, w = tid >> 5;
    const int s0 = blockIdx.x * 128;
    const int bh = blockIdx.y;
    const int b = bh / NH, h = bh % NH;
    const uint32_t lm = (lane & 15) * 80 + ((lane >> 4) << 4);

    // ---- async load q tile (128 rows x 64 K, hi+lo) ----
    const __half* qhg = g_qe_hi + ((size_t)bh * S_LEN + s0) * DH;
    const __half* qlg = g_qe_lo + ((size_t)bh * S_LEN + s0) * DH;
    #pragma unroll
    for (int l = 0; l < 4; ++l) {
        int i = tid + l * 256;            // [0,1024): r=i/8, q=i%8
        int r = i >> 3, q = i & 7;
        int kc = q >> 2, qq = q & 3;
        CP_ASYNC16(sb + FL_QOFF + kc*10240 + r*80 + qq*16, qhg + (size_t)r*DH + kc*32 + qq*8);
        CP_ASYNC16(sb + FL_QOFF + FL_QLO + kc*10240 + r*80 + qq*16, qlg + (size_t)r*DH + kc*32 + qq*8);
    }
    CP_COMMIT();

    // kv chunk loader: 64 t-rows of k hi (K=64) + 64 d-rows of V^T hi (t-chunk 64)
    auto load_kv = [&](int c, int buf) {
        const uint32_t kb = sb + buf * FL_KV;
        const __half* khg = g_ke_hi + ((size_t)bh * S_LEN + c*64) * DH;
        #pragma unroll
        for (int l = 0; l < 2; ++l) {
            int i = tid + l * 256;        // [0,512): r=i/8, q=i%8
            int r = i >> 3, q = i & 7;
            int kc = q >> 2, qq = q & 3;
            CP_ASYNC16(kb + kc*5120 + r*80 + qq*16, khg + (size_t)r*DH + kc*32 + qq*8);
        }
        const __half* vhg = g_vt_hi + (size_t)bh * DH * S_LEN + c*64;
        #pragma unroll
        for (int l = 0; l < 2; ++l) {
            int i = tid + l * 256;        // [0,512): r=i/8, q=i%8
            int r = i >> 3, q = i & 7;
            int kc = q >> 2, qq = q & 3;
            CP_ASYNC16(kb + FL_VHI + kc*5120 + r*80 + qq*16, vhg + (size_t)r*S_LEN + kc*32 + qq*8);
        }
        CP_COMMIT();
    };

    load_kv(0, 0);
    asm volatile("cp.async.wait_group 0;" ::: "memory");
    __syncthreads();

    // ---- extract q A-fragments into registers (4 k16-slices, hi+lo) ----
    uint32_t aqh[4][4], aql[4][4];
    #pragma unroll
    for (int ks4 = 0; ks4 < 4; ++ks4) {
        int kc = ks4 >> 1, ks = ks4 & 1;
        ldm_x4(aqh[ks4], sb + FL_QOFF + kc*10240 + (w*16)*80 + lm + ks*32);
        ldm_x4(aql[ks4], sb + FL_QOFF + FL_QLO + kc*10240 + (w*16)*80 + lm + ks*32);
    }

    // pos_sim row pointers for this thread's two C-fragment rows
    const float* pr0 = g_possim + ((size_t)b * S_LEN + (s0 + w*16 + (lane >> 2))) * S_LEN + (lane & 3) * 2;
    const float* pr1 = pr0 + (size_t)8 * S_LEN;

    float octx[8][4] = {};
    float m0 = -1e30f, m1 = -1e30f, l0 = 0.f, l1 = 0.f;
    const int NC = S_LEN / 64;

    for (int c = 0; c < NC; ++c) {
        const int buf = c & 1;
        if (c + 1 < NC) {
            load_kv(c + 1, buf ^ 1);
            asm volatile("cp.async.wait_group 1;" ::: "memory");
        } else {
            asm volatile("cp.async.wait_group 0;" ::: "memory");
        }
        __syncthreads();
        const uint32_t kb = sb + buf * FL_KV;

        // ---- QK: P[16 x 64] = q * k^T  (2-pass split on q, K=64) ----
        float ps[8][4] = {};
        #pragma unroll
        for (int ks4 = 0; ks4 < 4; ++ks4) {
            int kc = ks4 >> 1, ks = ks4 & 1;
            uint32_t bh4[4][4];
            #pragma unroll
            for (int ng = 0; ng < 4; ++ng)
                ldm_x4(bh4[ng], kb + kc*5120 + (ng*16)*80 + lm + ks*32);
            #pragma unroll
            for (int ng = 0; ng < 4; ++ng) {
                mma16816(ps[2*ng],   aqh[ks4], bh4[ng][0], bh4[ng][2]);
                mma16816(ps[2*ng+1], aqh[ks4], bh4[ng][1], bh4[ng][3]);
                mma16816(ps[2*ng],   aql[ks4], bh4[ng][0], bh4[ng][2]);
                mma16816(ps[2*ng+1], aql[ks4], bh4[ng][1], bh4[ng][3]);
            }
        }

        // ---- add pos_sim (exact fp32, from L2-resident gmem) ----
        {
            const float* p0 = pr0 + c * 64;
            const float* p1 = pr1 + c * 64;
            #pragma unroll
            for (int ng = 0; ng < 8; ++ng) {
                float2 a0 = *(const float2*)(p0 + ng * 8);
                float2 a1 = *(const float2*)(p1 + ng * 8);
                ps[ng][0] += a0.x; ps[ng][1] += a0.y;
                ps[ng][2] += a1.x; ps[ng][3] += a1.y;
            }
        }

        // ---- online softmax (rows: half0 = lane/4, half1 = +8) ----
        float mx0 = -1e30f, mx1 = -1e30f;
        #pragma unroll
        for (int ng = 0; ng < 8; ++ng) {
            mx0 = fmaxf(mx0, fmaxf(ps[ng][0], ps[ng][1]));
            mx1 = fmaxf(mx1, fmaxf(ps[ng][2], ps[ng][3]));
        }
        mx0 = fmaxf(mx0, __shfl_xor_sync(0xffffffffu, mx0, 1));
        mx0 = fmaxf(mx0, __shfl_xor_sync(0xffffffffu, mx0, 2));
        mx1 = fmaxf(mx1, __shfl_xor_sync(0xffffffffu, mx1, 1));
        mx1 = fmaxf(mx1, __shfl_xor_sync(0xffffffffu, mx1, 2));
        float mn0 = fmaxf(m0, mx0), mn1 = fmaxf(m1, mx1);
        float sc0 = __expf(m0 - mn0), sc1 = __expf(m1 - mn1);
        m0 = mn0; m1 = mn1;
        l0 *= sc0; l1 *= sc1;
        #pragma unroll
        for (int ng = 0; ng < 8; ++ng) {
            octx[ng][0] *= sc0; octx[ng][1] *= sc0;
            octx[ng][2] *= sc1; octx[ng][3] *= sc1;
        }
        float rs0 = 0.f, rs1 = 0.f;
        #pragma unroll
        for (int ng = 0; ng < 8; ++ng) {
            ps[ng][0] = __expf(ps[ng][0] - mn0);
            ps[ng][1] = __expf(ps[ng][1] - mn0);
            ps[ng][2] = __expf(ps[ng][2] - mn1);
            ps[ng][3] = __expf(ps[ng][3] - mn1);
            rs0 += ps[ng][0] + ps[ng][1];
            rs1 += ps[ng][2] + ps[ng][3];
        }
        rs0 += __shfl_xor_sync(0xffffffffu, rs0, 1);
        rs0 += __shfl_xor_sync(0xffffffffu, rs0, 2);
        rs1 += __shfl_xor_sync(0xffffffffu, rs1, 1);
        rs1 += __shfl_xor_sync(0xffffffffu, rs1, 2);
        l0 += rs0; l1 += rs1;

        // ---- register C-frag -> A-frag conversion (P hi only) ----
        uint32_t aph[4][4];
        #pragma unroll
        for (int kj = 0; kj < 4; ++kj) {
            #pragma unroll
            for (int q = 0; q < 4; ++q) {
                int nb = 2*kj + (q >> 1);
                float e0 = ps[nb][(q & 1) * 2 + 0];
                float e1 = ps[nb][(q & 1) * 2 + 1];
                aph[kj][q] = pack_f16x2(e0, e1);
            }
        }

        // ---- PV: ctx += P * V  (single-pass), B = V^T hi ----
        #pragma unroll
        for (int kj = 0; kj < 4; ++kj) {
            int kc = kj >> 1, ks = kj & 1;
            uint32_t vh4[4][4];
            #pragma unroll
            for (int ng = 0; ng < 4; ++ng)
                ldm_x4(vh4[ng], kb + FL_VHI + kc*5120 + (ng*16)*80 + lm + ks*32);
            #pragma unroll
            for (int ng = 0; ng < 4; ++ng) {
                mma16816(octx[2*ng],   aph[kj], vh4[ng][0], vh4[ng][2]);
                mma16816(octx[2*ng+1], aph[kj], vh4[ng][1], vh4[ng][3]);
            }
        }
        __syncthreads();
    }

    // ---- epilogue: normalize, write ctx hi (layout [(s*B+b)*E + h*64 + d]) ----
    float i0 = 1.f / l0, i1 = 1.f / l1;
    const int g = lane >> 2;
    #pragma unroll
    for (int half_ = 0; half_ < 2; ++half_) {
        const int s = s0 + w * 16 + g + half_ * 8;
        const float ih = half_ ? i1 : i0;
        size_t base = ((size_t)s * BATCH + b) * EMB + h * DH;
        #pragma unroll
        for (int ng = 0; ng < 8; ++ng) {
            int col = ng * 8 + (lane & 3) * 2;
            float v0 = octx[ng][half_*2+0] * ih;
            float v1 = octx[ng][half_*2+1] * ih;
            __half2 hh; hh.x = __float2half(v0); hh.y = __float2half(v1);
            *(__half2*)(g_ctx_hi + base + col) = hh;
        }
    }
}

// ---------------- out = LayerNorm(A + B), optional fp16 hi emission ----------------
template<bool SPLIT>
__global__ __launch_bounds__(256) void k_ln(const float* __restrict__ A,
                                            const float* __restrict__ Bv,
                                            const float* __restrict__ gam,
                                            const float* __restrict__ bet,
                                            float* __restrict__ out,
                                            __half* __restrict__ ohi) {
    __shared__ float red[8];
    size_t row = blockIdx.x;
    const float* a = A + row * EMB;
    const float* b = Bv + row * EMB;
    int tid = threadIdx.x;
    int lane = tid & 31, wid = tid >> 5;
    float v[4];
    float sum = 0.f;
    #pragma unroll
    for (int i = 0; i < 4; ++i) { v[i] = a[tid + i*256] + b[tid + i*256]; sum += v[i]; }
    sum = warp_sum(sum);
    if (lane == 0) red[wid] = sum;
    __syncthreads();
    if (wid == 0) {
        float t = (lane < 8) ? red[lane] : 0.f;
        t = warp_sum(t);
        if (lane == 0) red[0] = t;
    }
    __syncthreads();
    float mu = red[0] * (1.0f / EMB);
    __syncthreads();
    float sq = 0.f;
    #pragma unroll
    for (int i = 0; i < 4; ++i) { float d = v[i] - mu; sq += d * d; }
    sq = warp_sum(sq);
    if (lane == 0) red[wid] = sq;
    __syncthreads();
    if (wid == 0) {
        float t = (lane < 8) ? red[lane] : 0.f;
        t = warp_sum(t);
        if (lane == 0) red[0] = t;
    }
    __syncthreads();
    float inv = rsqrtf(red[0] * (1.0f / EMB) + 1e-5f);
    #pragma unroll
    for (int i = 0; i < 4; ++i) {
        int c = tid + i*256;
        float o = (v[i] - mu) * inv * gam[c] + bet[c];
        out[row * EMB + c] = o;
        if (SPLIT) {
            ohi[row * EMB + c] = __float2half(o);
        }
    }
}

// ---------------- launch ----------------
extern "C" void kernel_launch(void* const* d_in, const int* in_sizes, int n_in,
                              void* d_out, int out_size) {
    const float* src       = (const float*)d_in[0];
    const float* pos_embed = (const float*)d_in[1];
    const float* in_proj_w = (const float*)d_in[2];
    const float* in_proj_b = (const float*)d_in[3];
    const float* out_w     = (const float*)d_in[4];
    const float* out_b     = (const float*)d_in[5];
    const float* lin1_w    = (const float*)d_in[6];
    const float* lin1_b    = (const float*)d_in[7];
    const float* lin2_w    = (const float*)d_in[8];
    const float* lin2_b    = (const float*)d_in[9];
    const float* ln1_g     = (const float*)d_in[10];
    const float* ln1_b     = (const float*)d_in[11];
    const float* ln2_g     = (const float*)d_in[12];
    const float* ln2_b     = (const float*)d_in[13];
    const float* pos_w     = (const float*)d_in[14];
    const float* pos_b     = (const float*)d_in[15];
    float* out = (float*)d_out;

    float *p_qkv, *p_tmp, *p_x;
    __half *p_src_hi, *p_ctx_hi, *p_x_hi, *p_ff1_hi;
    __half *p_ipw_hi, *p_outw_hi, *p_l1w_hi, *p_l2w_hi;
    cudaGetSymbolAddress((void**)&p_qkv, g_qkv);
    cudaGetSymbolAddress((void**)&p_tmp, g_tmp);
    cudaGetSymbolAddress((void**)&p_x,   g_x);
    cudaGetSymbolAddress((void**)&p_src_hi, g_src_hi);
    cudaGetSymbolAddress((void**)&p_ctx_hi, g_ctx_hi);
    cudaGetSymbolAddress((void**)&p_x_hi,   g_x_hi);
    cudaGetSymbolAddress((void**)&p_ff1_hi, g_ff1_hi);
    cudaGetSymbolAddress((void**)&p_ipw_hi, g_ipw_hi);
    cudaGetSymbolAddress((void**)&p_outw_hi, g_outw_hi);
    cudaGetSymbolAddress((void**)&p_l1w_hi, g_l1w_hi);
    cudaGetSymbolAddress((void**)&p_l2w_hi, g_l2w_hi);

    cudaFuncSetAttribute(hmma_gemm<false,false,true>, cudaFuncAttributeMaxDynamicSharedMemorySize, GT_SMEM);
    cudaFuncSetAttribute(hmma_gemm<true,true,false>,  cudaFuncAttributeMaxDynamicSharedMemorySize, GT_SMEM);
    cudaFuncSetAttribute(k_flash, cudaFuncAttributeMaxDynamicSharedMemorySize, FL_SMEM);

    auto split_hi = [&](const float* p, __half* hi, size_t n) {
        int n4 = (int)(n / 4);
        k_split_hi<<<(n4 + 255) / 256, 256>>>((const float4*)p, (__half2*)hi, n4);
    };

    // weight + input conversions (launches 1-5)
    split_hi(in_proj_w, p_ipw_hi,  (size_t)3*EMB*EMB);
    split_hi(out_w,     p_outw_hi, (size_t)EMB*EMB);
    split_hi(lin1_w,    p_l1w_hi,  (size_t)FF*EMB);
    split_hi(lin2_w,    p_l2w_hi,  (size_t)EMB*FF);
    split_hi(src,       p_src_hi,  (size_t)NROWS*EMB);

    // qkv projection (launch 6)
    hmma_gemm<false,false,true><<<dim3(3*EMB/128, NROWS/128), 256, GT_SMEM>>>(
        p_src_hi, p_ipw_hi, in_proj_b,
        p_qkv, nullptr, NROWS, 3*EMB, EMB);

    // positional path: pe -> L1 norm -> exact pos_sim (fp32)
    k_pe<<<(BATCH*PP*S_LEN + 255)/256, 256>>>(pos_embed, pos_w, pos_b);
    k_l1<<<(BATCH*S_LEN + 255)/256, 256>>>();
    k_possim<<<dim3(S_LEN/64, S_LEN/64, BATCH), 256>>>();

    // attention operand prep + fused flash attention
    k_prepqk<<<(BH*S_LEN*16 + 255)/256, 256>>>();
    k_prepv<<<(BH*DH*(S_LEN/4) + 255)/256, 256>>>();
    k_flash<<<dim3(S_LEN/128, BH), 256, FL_SMEM>>>();

    // output projection + LN1
    hmma_gemm<false,false,true><<<dim3(EMB/128, NROWS/128), 256, GT_SMEM>>>(
        p_ctx_hi, p_outw_hi, out_b,
        p_tmp, nullptr, NROWS, EMB, EMB);
    k_ln<true><<<NROWS, 256>>>(src, p_tmp, ln1_g, ln1_b, p_x, p_x_hi);

    // FFN + LN2
    hmma_gemm<true,true,false><<<dim3(FF/128, NROWS/128), 256, GT_SMEM>>>(
        p_x_hi, p_l1w_hi, lin1_b,
        nullptr, p_ff1_hi, NROWS, FF, EMB);
    hmma_gemm<false,false,true><<<dim3(EMB/128, NROWS/128), 256, GT_SMEM>>>(
        p_ff1_hi, p_l2w_hi, lin2_b,
        p_tmp, nullptr, NROWS, EMB, FF);
    k_ln<false><<<NROWS, 256>>>(p_x, p_tmp, ln2_g, ln2_b, out, nullptr);
}